// round 14
// baseline (speedup 1.0000x reference)
#include <cuda_runtime.h>
#include <cuda_fp16.h>
#include <cstdint>
#include <cmath>

// Problem constants
#define BB   128
#define LL   400
#define TT   30
#define EE   300
#define HE   512
#define HD   512
#define AA   512
#define VV   20000
#define PAD_ID 0
#define UNK_ID 1
#define SOS_ID 2

#define STAGES 4
#define SK     40                      // smem row stride in halfs (32 + 8 pad)
#define SMEM_GEMM (2 * STAGES * 64 * SK * 2)   // 40960 bytes (64x64 tiles)
#define SMEM_STEP (2 * 2 * 128 * SK * 2)       // 40960 bytes (128x128, 2-stage)
#define CH1 15                         // tail chunk 1 = steps [0, CH1)

// ---------------------------------------------------------------------------
// Scratch (device globals; distinct symbols only, all 256B aligned)
// ---------------------------------------------------------------------------
__device__ __align__(256) __half g_enc_h [(size_t)BB * LL * HE];     // 52 MB
__device__ __align__(256) __half g_proj_h[(size_t)BB * LL * AA];     // 52 MB
__device__ __align__(256) __half g_embed_h[(size_t)VV * 304];        // 12 MB
__device__ __align__(256) __half g_Wih_e[1536 * 304];
__device__ __align__(256) __half g_Wih_c[1536 * 512];
__device__ __align__(256) __half g_Whh  [1536 * 512];
__device__ __align__(256) __half g_Ws   [512 * 512];
__device__ __align__(256) __half g_Wh   [512 * 512];
__device__ __align__(256) __half g_Wr_e [512 * 304];
__device__ __align__(256) __half g_Wr_c [512 * 1024];
__device__ __align__(256) __half g_Wo   [(size_t)VV * 256];
__device__ __align__(256) float  g_giemb[(size_t)TT * BB * 1536];    // 23.6 MB
__device__ __align__(256) float  g_rvemb[(size_t)TT * BB * 512];     // 7.9 MB
__device__ __align__(256) float  g_gi_p [4 * BB * 1536];
__device__ __align__(256) float  g_gh_p [4 * BB * 1536];
__device__ __align__(256) float  g_qp   [4 * BB * 512];
// Per-step ring buffers
__device__ __align__(256) float  g_sf  [(size_t)(TT + 1) * BB * HD];
__device__ __align__(256) __half g_shh [(size_t)(TT + 1) * BB * HD];
__device__ __align__(256) __half g_chh [(size_t)(TT + 1) * BB * HE];
__device__ __align__(256) float  g_attnb[(size_t)TT * BB * LL];
__device__ __align__(256) float  g_pcb  [TT * BB];
// Batched tail buffers
__device__ __align__(256) float  g_rv_all [(size_t)TT * BB * 512];   // 7.9 MB
__device__ __align__(256) __half g_mh_all [(size_t)TT * BB * 256];   // 2 MB
__device__ __align__(256) float  g_energy_all[(size_t)TT * BB * VV]; // 307 MB
// Phase counters: [0..TT) gates, [TT..2TT) gru, [2TT..3TT) q. Zeroed per call.
__device__ __align__(256) unsigned g_cnt[3 * TT];

// ---------------------------------------------------------------------------
// Low-level helpers
// ---------------------------------------------------------------------------
__device__ __forceinline__ void cp_async16(uint32_t dst, const void* src, int bytes) {
    asm volatile("cp.async.ca.shared.global [%0], [%1], 16, %2;\n"
                 :: "r"(dst), "l"(src), "r"(bytes));
}
__device__ __forceinline__ void cp_commit() {
    asm volatile("cp.async.commit_group;\n" ::: "memory");
}
template <int N>
__device__ __forceinline__ void cp_wait() {
    asm volatile("cp.async.wait_group %0;\n" :: "n"(N) : "memory");
}

__device__ __forceinline__ void ldsm4(uint32_t (&r)[4], uint32_t addr) {
    asm volatile("ldmatrix.sync.aligned.m8n8.x4.shared.b16 {%0,%1,%2,%3}, [%4];"
                 : "=r"(r[0]), "=r"(r[1]), "=r"(r[2]), "=r"(r[3]) : "r"(addr));
}

__device__ __forceinline__ void mma_f16(float (&c)[4], const uint32_t (&a)[4],
                                        uint32_t b0, uint32_t b1) {
    asm volatile(
        "mma.sync.aligned.m16n8k16.row.col.f32.f16.f16.f32 "
        "{%0,%1,%2,%3}, {%4,%5,%6,%7}, {%8,%9}, {%0,%1,%2,%3};\n"
        : "+f"(c[0]), "+f"(c[1]), "+f"(c[2]), "+f"(c[3])
        : "r"(a[0]), "r"(a[1]), "r"(a[2]), "r"(a[3]), "r"(b0), "r"(b1));
}

// Acquire-load poll (L2 read, no RMW serialization)
__device__ __forceinline__ unsigned ld_acq(const unsigned* p) {
    unsigned v;
    asm volatile("ld.acquire.gpu.global.u32 %0, [%1];"
                 : "=r"(v) : "l"(p) : "memory");
    return v;
}

// f16x2 ops for the attention scores phase
__device__ __forceinline__ uint32_t hadd2_(uint32_t a, uint32_t b) {
    uint32_t d;
    asm("add.f16x2 %0, %1, %2;" : "=r"(d) : "r"(a), "r"(b));
    return d;
}
__device__ __forceinline__ uint32_t hfma2_(uint32_t a, uint32_t b, uint32_t c) {
    uint32_t d;
    asm("fma.rn.f16x2 %0, %1, %2, %3;" : "=r"(d) : "r"(a), "r"(b), "r"(c));
    return d;
}
__device__ __forceinline__ uint32_t tanh2_(uint32_t x) {
    uint32_t d;
    asm("tanh.approx.f16x2 %0, %1;" : "=r"(d) : "r"(x));
    return d;
}

__device__ __forceinline__ float sigmoid_fast(float x) {
    return __fdividef(1.0f, 1.0f + __expf(-x));
}
__device__ __forceinline__ float tanh_fast(float x) {
    x = fminf(15.0f, fmaxf(-15.0f, x));
    float e = __expf(2.0f * x);
    return 1.0f - __fdividef(2.0f, e + 1.0f);
}

__device__ __forceinline__ float warpMax(float v) {
    #pragma unroll
    for (int o = 16; o; o >>= 1) v = fmaxf(v, __shfl_xor_sync(0xffffffffu, v, o));
    return v;
}
__device__ __forceinline__ float warpSum(float v) {
    #pragma unroll
    for (int o = 16; o; o >>= 1) v += __shfl_xor_sync(0xffffffffu, v, o);
    return v;
}
__device__ __forceinline__ float blockMax(float v, float* red) {
    v = warpMax(v);
    int w = threadIdx.x >> 5, l = threadIdx.x & 31, nw = blockDim.x >> 5;
    if (l == 0) red[w] = v;
    __syncthreads();
    if (threadIdx.x < 32) {
        float x = (threadIdx.x < nw) ? red[threadIdx.x] : -INFINITY;
        x = warpMax(x);
        if (threadIdx.x == 0) red[0] = x;
    }
    __syncthreads();
    v = red[0];
    __syncthreads();
    return v;
}
__device__ __forceinline__ float blockSum(float v, float* red) {
    v = warpSum(v);
    int w = threadIdx.x >> 5, l = threadIdx.x & 31, nw = blockDim.x >> 5;
    if (l == 0) red[w] = v;
    __syncthreads();
    if (threadIdx.x < 32) {
        float x = (threadIdx.x < nw) ? red[threadIdx.x] : 0.0f;
        x = warpSum(x);
        if (threadIdx.x == 0) red[0] = x;
    }
    __syncthreads();
    v = red[0];
    __syncthreads();
    return v;
}

// ---------------------------------------------------------------------------
// cvt_all: every fp32->fp16 repack + s copy + zeroing, in ONE launch.
// ---------------------------------------------------------------------------
struct CvtArgs {
    const float* enc;
    const float* embed;
    const float* W_ih;
    const float* W_hh;
    const float* att_Ws;
    const float* att_Wh;
    const float* read_W;
    const float* read_Wo;
    const float* s_in;
};

__device__ __forceinline__ void cvt_job(
    const float* __restrict__ src, __half* __restrict__ dst,
    int rows, int sstr, int soff, int dstr, int clen)
{
    int total = rows * dstr;
    for (int i = blockIdx.x * blockDim.x + threadIdx.x; i < total;
         i += gridDim.x * blockDim.x) {
        int r = i / dstr, c = i - r * dstr;
        float v = (c < clen) ? src[(size_t)r * sstr + soff + c] : 0.0f;
        dst[i] = __float2half(v);
    }
}

__global__ __launch_bounds__(256) void cvt_all(CvtArgs a) {
    switch (blockIdx.y) {
    case 0:  cvt_job(a.enc,     g_enc_h,   BB * LL, 512, 0, 512, 512); break;
    case 1:  cvt_job(a.embed,   g_embed_h, VV, 300, 0, 304, 300); break;
    case 2:  cvt_job(a.W_ih,    g_Wih_e,   1536, 812, 0, 304, 300); break;
    case 3:  cvt_job(a.W_ih,    g_Wih_c,   1536, 812, 300, 512, 512); break;
    case 4:  cvt_job(a.W_hh,    g_Whh,     1536, 512, 0, 512, 512); break;
    case 5:  cvt_job(a.att_Ws,  g_Ws,      512, 512, 0, 512, 512); break;
    case 6:  cvt_job(a.att_Wh,  g_Wh,      512, 512, 0, 512, 512); break;
    case 7:  cvt_job(a.read_W,  g_Wr_e,    512, 1324, 0, 304, 300); break;
    case 8:  cvt_job(a.read_W,  g_Wr_c,    512, 1324, 300, 1024, 1024); break;
    case 9:  cvt_job(a.read_Wo, g_Wo,      VV, 256, 0, 256, 256); break;
    case 10: cvt_job(a.s_in,    g_shh,     BB, 512, 0, 512, 512); break;
    case 11: {
        for (int i = blockIdx.x * blockDim.x + threadIdx.x; i < BB * HD;
             i += gridDim.x * blockDim.x)
            g_sf[i] = a.s_in[i];
        break;
    }
    case 12: {
        for (int i = blockIdx.x * blockDim.x + threadIdx.x; i < BB * HE;
             i += gridDim.x * blockDim.x)
            g_chh[i] = __float2half(0.0f);
        break;
    }
    default: {
        for (int i = blockIdx.x * blockDim.x + threadIdx.x; i < 3 * TT;
             i += gridDim.x * blockDim.x)
            g_cnt[i] = 0u;
        break;
    }
    }
}

// ---------------------------------------------------------------------------
// 64x64-tile fp16 GEMM (128 threads), explicit tile coords
// ---------------------------------------------------------------------------
struct GH {
    const __half* A; int lda;
    const __half* W; int ldw;
    float* C; int ldc;
    int N;
    int kbeg, kend;
    const __half* embed;
    const int*    tgt;
    const __half* ctx;
    const __half* s;
};

#define MODE_PLAIN 0
#define MODE_EMB   1
#define MODE_CS    2

template <int MODE, bool OUTH>
__device__ __forceinline__ void grun(const GH& g, int mt0, int nt0) {
    extern __shared__ __half smh[];
    __half* As = smh;
    __half* Ws = smh + STAGES * 64 * SK;

    const int tid = threadIdx.x, lane = tid & 31, warp = tid >> 5;
    const int wm = warp >> 1, wn = warp & 1;

    const int r0 = tid >> 2, kc = (tid & 3) * 8;
    const int r1 = r0 + 32;
    const int gm0 = mt0 + r0, gm1 = mt0 + r1;
    const int gn0 = nt0 + r0, gn1 = nt0 + r1;

    const __half *a0 = nullptr, *a1 = nullptr;
    const __half *c0p = nullptr, *c1p = nullptr, *s0p = nullptr, *s1p = nullptr;
    if (MODE == MODE_PLAIN) {
        a0 = g.A + (size_t)gm0 * g.lda;
        a1 = g.A + (size_t)gm1 * g.lda;
    } else if (MODE == MODE_EMB) {
        int t0 = gm0 >> 7, b0 = gm0 & 127;
        int w0 = (t0 == 0) ? SOS_ID : g.tgt[b0 * TT + t0 - 1];
        if (w0 >= VV) w0 = UNK_ID;
        int t1 = gm1 >> 7, b1 = gm1 & 127;
        int w1 = (t1 == 0) ? SOS_ID : g.tgt[b1 * TT + t1 - 1];
        if (w1 >= VV) w1 = UNK_ID;
        a0 = g.embed + (size_t)w0 * 304;
        a1 = g.embed + (size_t)w1 * 304;
    } else {
        c0p = g.ctx + (size_t)gm0 * 512; c1p = g.ctx + (size_t)gm1 * 512;
        s0p = g.s   + (size_t)gm0 * 512; s1p = g.s   + (size_t)gm1 * 512;
    }
    const bool n0ok = (gn0 < g.N), n1ok = (gn1 < g.N);
    const __half* w0p = g.W + (size_t)(n0ok ? gn0 : 0) * g.ldw;
    const __half* w1p = g.W + (size_t)(n1ok ? gn1 : 0) * g.ldw;

    const uint32_t asB = (uint32_t)__cvta_generic_to_shared(As);
    const uint32_t wsB = (uint32_t)__cvta_generic_to_shared(Ws);
    const int STB = 64 * SK * 2;
    const uint32_t aD0 = asB + (r0 * SK + kc) * 2;
    const uint32_t aD1 = asB + (r1 * SK + kc) * 2;
    const uint32_t wD0 = wsB + (r0 * SK + kc) * 2;
    const uint32_t wD1 = wsB + (r1 * SK + kc) * 2;

    const int nk = (g.kend - g.kbeg + 31) >> 5;

    auto pf = [&](int i) {
        int kg = g.kbeg + i * 32 + kc;
        int buf = (i & 3) * STB;
        bool v = kg < g.kend;
        const __half *sa0, *sa1;
        if (MODE == MODE_CS) {
            sa0 = (kg < 512) ? c0p + kg : s0p + (kg - 512);
            sa1 = (kg < 512) ? c1p + kg : s1p + (kg - 512);
        } else {
            sa0 = a0 + kg; sa1 = a1 + kg;
        }
        if (!v) { sa0 = g.W; sa1 = g.W; }
        cp_async16(aD0 + buf, sa0, v ? 16 : 0);
        cp_async16(aD1 + buf, sa1, v ? 16 : 0);
        bool v0 = v && n0ok, v1 = v && n1ok;
        cp_async16(wD0 + buf, v0 ? (w0p + kg) : g.W, v0 ? 16 : 0);
        cp_async16(wD1 + buf, v1 ? (w1p + kg) : g.W, v1 ? 16 : 0);
    };

    #pragma unroll
    for (int p = 0; p < 3; p++) {
        if (p < nk) pf(p);
        cp_commit();
    }

    float c[2][4][4] = {};
    const int lr = lane & 15, lk = (lane >> 4) * 8;

    for (int i = 0; i < nk; i++) {
        if (i + 3 < nk) pf(i + 3);
        cp_commit();
        cp_wait<3>();
        __syncthreads();

        const uint32_t ab = asB + (i & 3) * STB;
        const uint32_t wb = wsB + (i & 3) * STB;

        #pragma unroll
        for (int kk = 0; kk < 32; kk += 16) {
            uint32_t a[2][4], bb[2][4];
            #pragma unroll
            for (int mt = 0; mt < 2; mt++)
                ldsm4(a[mt], ab + ((wm * 32 + mt * 16 + lr) * SK + kk + lk) * 2);
            #pragma unroll
            for (int n2 = 0; n2 < 2; n2++)
                ldsm4(bb[n2], wb + ((wn * 32 + n2 * 16 + lr) * SK + kk + lk) * 2);
            #pragma unroll
            for (int mt = 0; mt < 2; mt++)
                #pragma unroll
                for (int ns = 0; ns < 4; ns++) {
                    int n2 = ns >> 1, sel = ns & 1;
                    mma_f16(c[mt][ns], a[mt], bb[n2][sel], bb[n2][sel + 2]);
                }
        }
        __syncthreads();
    }

    const int gr = lane >> 2, gc = (lane & 3) * 2;
    #pragma unroll
    for (int mt = 0; mt < 2; mt++)
        #pragma unroll
        for (int ns = 0; ns < 4; ns++) {
            int row = mt0 + wm * 32 + mt * 16 + gr;
            int col = nt0 + wn * 32 + ns * 8 + gc;
            if (col < g.N) {
                if (OUTH) {
                    __half* Ch = (__half*)g.C;
                    Ch[(size_t)row * g.ldc + col]           = __float2half(c[mt][ns][0]);
                    Ch[(size_t)row * g.ldc + col + 1]       = __float2half(c[mt][ns][1]);
                    Ch[(size_t)(row + 8) * g.ldc + col]     = __float2half(c[mt][ns][2]);
                    Ch[(size_t)(row + 8) * g.ldc + col + 1] = __float2half(c[mt][ns][3]);
                } else {
                    g.C[(size_t)row * g.ldc + col]           = c[mt][ns][0];
                    g.C[(size_t)row * g.ldc + col + 1]       = c[mt][ns][1];
                    g.C[(size_t)(row + 8) * g.ldc + col]     = c[mt][ns][2];
                    g.C[(size_t)(row + 8) * g.ldc + col + 1] = c[mt][ns][3];
                }
            }
        }
}

__global__ __launch_bounds__(128) void k_g_plain(GH g) {
    grun<MODE_PLAIN, false>(g, blockIdx.y * 64, blockIdx.x * 64);
}
__global__ __launch_bounds__(128) void k_g_cs(GH g) {
    grun<MODE_CS, false>(g, blockIdx.y * 64, blockIdx.x * 64);
}

// All three precompute GEMMs in ONE launch (flattened grid)
__global__ __launch_bounds__(128) void k_uber(GH gp, GH ge, GH gr) {
    int bid = blockIdx.x;
    if (bid < 6400) {           // proj: 8 x 800 tiles
        grun<MODE_PLAIN, true>(gp, (bid / 8) * 64, (bid % 8) * 64);
    } else if (bid < 7840) {    // giemb: 24 x 60 tiles
        int j = bid - 6400;
        grun<MODE_EMB, false>(ge, (j / 24) * 64, (j % 24) * 64);
    } else {                    // rvemb: 8 x 60 tiles
        int j = bid - 7840;
        grun<MODE_EMB, false>(gr, (j / 8) * 64, (j % 8) * 64);
    }
}

// ---------------------------------------------------------------------------
// 128x128-tile fp16 GEMM (512 threads, 2-stage) — used inside step_kernel.
// ---------------------------------------------------------------------------
__device__ __forceinline__ void grun512(
    const __half* __restrict__ A, int lda,
    const __half* __restrict__ W, int ldw,
    float* __restrict__ C, int ldc, int N,
    int kbeg, int kend, int nt0)
{
    extern __shared__ __half smh[];
    __half* As = smh;
    __half* Ws = smh + 2 * 128 * SK;

    const int tid = threadIdx.x, lane = tid & 31, warp = tid >> 5;
    const int wm = warp >> 2, wn = warp & 3;

    const int r = tid >> 2, kc = (tid & 3) * 8;
    const __half* aRow = A + (size_t)r * lda;
    const int gn = nt0 + r;
    const bool nok = (gn < N);
    const __half* wRow = W + (size_t)(nok ? gn : 0) * ldw;

    const uint32_t asB = (uint32_t)__cvta_generic_to_shared(As);
    const uint32_t wsB = (uint32_t)__cvta_generic_to_shared(Ws);
    const int STB = 128 * SK * 2;
    const uint32_t aD = asB + (r * SK + kc) * 2;
    const uint32_t wD = wsB + (r * SK + kc) * 2;

    const int nk = (kend - kbeg + 31) >> 5;

    auto pf = [&](int i) {
        int kg = kbeg + i * 32 + kc;
        int buf = (i & 1) * STB;
        bool v = kg < kend;
        cp_async16(aD + buf, v ? (const void*)(aRow + kg) : (const void*)W,
                   v ? 16 : 0);
        bool vw = v && nok;
        cp_async16(wD + buf, vw ? (const void*)(wRow + kg) : (const void*)W,
                   vw ? 16 : 0);
    };

    pf(0);
    cp_commit();

    float c[2][4][4] = {};
    const int lr = lane & 15, lk = (lane >> 4) * 8;

    for (int i = 0; i < nk; i++) {
        if (i + 1 < nk) pf(i + 1);
        cp_commit();
        cp_wait<1>();
        __syncthreads();

        const uint32_t ab = asB + (i & 1) * STB;
        const uint32_t wb = wsB + (i & 1) * STB;

        #pragma unroll
        for (int kk = 0; kk < 32; kk += 16) {
            uint32_t a[2][4], bb[2][4];
            #pragma unroll
            for (int mt = 0; mt < 2; mt++)
                ldsm4(a[mt], ab + ((wm * 32 + mt * 16 + lr) * SK + kk + lk) * 2);
            #pragma unroll
            for (int n2 = 0; n2 < 2; n2++)
                ldsm4(bb[n2], wb + ((wn * 32 + n2 * 16 + lr) * SK + kk + lk) * 2);
            #pragma unroll
            for (int mt = 0; mt < 2; mt++)
                #pragma unroll
                for (int ns = 0; ns < 4; ns++) {
                    int n2 = ns >> 1, sel = ns & 1;
                    mma_f16(c[mt][ns], a[mt], bb[n2][sel], bb[n2][sel + 2]);
                }
        }
        __syncthreads();
    }

    const int gr = lane >> 2, gc = (lane & 3) * 2;
    #pragma unroll
    for (int mt = 0; mt < 2; mt++)
        #pragma unroll
        for (int ns = 0; ns < 4; ns++) {
            int row = wm * 32 + mt * 16 + gr;
            int col = nt0 + wn * 32 + ns * 8 + gc;
            if (col < N) {
                C[(size_t)row * ldc + col]           = c[mt][ns][0];
                C[(size_t)row * ldc + col + 1]       = c[mt][ns][1];
                C[(size_t)(row + 8) * ldc + col]     = c[mt][ns][2];
                C[(size_t)(row + 8) * ldc + col + 1] = c[mt][ns][3];
            }
        }
}

// ---------------------------------------------------------------------------
// step_kernel: all 4 phases of one decoder step in one launch.
// bid 0..95 gates | 96..127 gru | 128..143 q | 144..271 attention
// ---------------------------------------------------------------------------
__global__ __launch_bounds__(512) void step_kernel(
    int t,
    const float* __restrict__ b_ih, const float* __restrict__ b_hh,
    const float* __restrict__ att_b, const float* __restrict__ vvec,
    const int*   __restrict__ src,
    const float* __restrict__ copy_W, const float* __restrict__ copy_b)
{
    __shared__ __align__(16) float es[LL];
    __shared__ float part[2][HE];
    __shared__ float red[32];

    const int bid = blockIdx.x, tid = threadIdx.x;
    const __half* shC = g_shh + (size_t)t * BB * HD;
    __half*       shN = g_shh + (size_t)(t + 1) * BB * HD;
    const __half* chC = g_chh + (size_t)t * BB * HE;
    __half*       chN = g_chh + (size_t)(t + 1) * BB * HE;
    const float*  sCur = g_sf + (size_t)t * BB * HD;
    float*        sNxt = g_sf + (size_t)(t + 1) * BB * HD;

    if (bid < 96) {
        // ---- Phase A: gates GEMMs ----
        int half = bid / 48, j = bid % 48;
        int sp = j / 12, nt = j % 12;
        const __half* A = half ? shC : chC;
        const __half* W = half ? g_Whh : g_Wih_c;
        float* C = (half ? g_gh_p : g_gi_p) + (size_t)sp * BB * 1536;
        grun512(A, 512, W, 512, C, 1536, 1536, sp * 128, sp * 128 + 128,
                nt * 128);
        __threadfence();
        __syncthreads();
        if (tid == 0) atomicAdd(&g_cnt[t], 1u);
    } else if (bid < 128) {
        // ---- Phase B: GRU ----
        if (tid == 0) {
            while (ld_acq(&g_cnt[t]) < 96u) __nanosleep(64);
        }
        __syncthreads();
        for (int i = (bid - 96) * 512 + tid; i < BB * HD; i += 32 * 512) {
            int b = i >> 9, h = i & 511;
            size_t ob = (size_t)b * 1536;
            size_t oe = ((size_t)t * BB + b) * 1536;
            float ir = g_giemb[oe + h]        + b_ih[h];
            float iz = g_giemb[oe + 512 + h]  + b_ih[512 + h];
            float in = g_giemb[oe + 1024 + h] + b_ih[1024 + h];
            float hr = b_hh[h], hz = b_hh[512 + h], hn = b_hh[1024 + h];
            #pragma unroll
            for (int z = 0; z < 4; z++) {
                size_t o = (size_t)z * BB * 1536 + ob;
                ir += g_gi_p[o + h];        iz += g_gi_p[o + 512 + h];
                in += g_gi_p[o + 1024 + h];
                hr += g_gh_p[o + h];        hz += g_gh_p[o + 512 + h];
                hn += g_gh_p[o + 1024 + h];
            }
            float r = sigmoid_fast(ir + hr);
            float z = sigmoid_fast(iz + hz);
            float n = tanh_fast(in + r * hn);
            float sn = (1.0f - z) * n + z * sCur[i];
            sNxt[i] = sn;
            shN[i] = __float2half(sn);
        }
        __threadfence();
        __syncthreads();
        if (tid == 0) atomicAdd(&g_cnt[TT + t], 1u);
    } else if (bid < 144) {
        // ---- Phase C: q split-K4 GEMM ----
        if (tid == 0) {
            while (ld_acq(&g_cnt[TT + t]) < 32u) __nanosleep(64);
        }
        __syncthreads();
        int j = bid - 128, sp = j >> 2, nt = j & 3;
        grun512(shN, 512, g_Ws, 512, g_qp + (size_t)sp * BB * 512, 512, 512,
                sp * 128, sp * 128 + 128, nt * 128);
        __threadfence();
        __syncthreads();
        if (tid == 0) atomicAdd(&g_cnt[2 * TT + t], 1u);
    } else {
        // ---- Phase D: attention (f16x2 scores) ----
        int b = bid - 144;
        if (tid == 0) {
            while (ld_acq(&g_cnt[2 * TT + t]) < 16u) __nanosleep(64);
        }
        __syncthreads();

        int warp = tid >> 5, lane = tid & 31;
        float* atT = g_attnb + (size_t)t * BB * LL;
        float* pcT = g_pcb + (size_t)t * BB;

        // q (bias + 4 partials) and v as half2 registers
        uint32_t qh[2][4], vh[2][4];
        #pragma unroll
        for (int j = 0; j < 2; j++) {
            int base = (lane + 32 * j) * 8;
            float qf[8];
            #pragma unroll
            for (int p = 0; p < 8; p++) qf[p] = att_b[base + p];
            #pragma unroll
            for (int z = 0; z < 4; z++) {
                const float* qz = g_qp + ((size_t)z * BB + b) * 512 + base;
                float4 q0 = *(const float4*)qz;
                float4 q1 = *(const float4*)(qz + 4);
                qf[0] += q0.x; qf[1] += q0.y; qf[2] += q0.z; qf[3] += q0.w;
                qf[4] += q1.x; qf[5] += q1.y; qf[6] += q1.z; qf[7] += q1.w;
            }
            #pragma unroll
            for (int p = 0; p < 4; p++) {
                __half2 h = __floats2half2_rn(qf[2 * p], qf[2 * p + 1]);
                qh[j][p] = *(uint32_t*)&h;
                __half2 vv2 = __floats2half2_rn(vvec[base + 2 * p],
                                                vvec[base + 2 * p + 1]);
                vh[j][p] = *(uint32_t*)&vv2;
            }
        }

        // scores: e[l] = sum v * tanh(proj + q), f16x2 math, fp32 reduce
        for (int l = warp; l < LL; l += 16) {
            const uint4* pp = (const uint4*)(g_proj_h + ((size_t)b * LL + l) * AA);
            uint32_t acc0 = 0u, acc1 = 0u;   // half2(0,0)
            #pragma unroll
            for (int j = 0; j < 2; j++) {
                uint4 pv = pp[lane + 32 * j];
                const uint32_t* h2 = (const uint32_t*)&pv;
                uint32_t& acc = (j == 0) ? acc0 : acc1;
                #pragma unroll
                for (int p = 0; p < 4; p++) {
                    uint32_t tt = tanh2_(hadd2_(h2[p], qh[j][p]));
                    acc = hfma2_(tt, vh[j][p], acc);
                }
            }
            float2 f0 = __half22float2(*(__half2*)&acc0);
            float2 f1 = __half22float2(*(__half2*)&acc1);
            float acc = (f0.x + f0.y) + (f1.x + f1.y);
            acc = warpSum(acc);
            if (lane == 0)
                es[l] = (src[b * LL + l] == PAD_ID) ? -1e30f : acc;
        }
        __syncthreads();

        // softmax over L
        float ev = (tid < LL) ? es[tid] : -INFINITY;
        float m  = blockMax(ev, red);
        float p  = (tid < LL) ? __expf(ev - m) : 0.0f;
        float Z  = blockSum(p, red);
        float a  = p / Z;
        if (tid < LL) { es[tid] = a; atT[b * LL + tid] = a; }
        __syncthreads();

        // ctx
        int gg = tid >> 8, cc = tid & 255;
        const __half2* eb = (const __half2*)(g_enc_h + (size_t)b * LL * HE) + cc;
        float ax = 0.0f, ay = 0.0f;
        int l0 = gg * 200;
        #pragma unroll 4
        for (int l = l0; l < l0 + 200; l++) {
            float2 f = __half22float2(eb[(size_t)l * 256]);
            ax += es[l] * f.x;
            ay += es[l] * f.y;
        }
        part[gg][2 * cc]     = ax;
        part[gg][2 * cc + 1] = ay;
        __syncthreads();

        float ctxv = part[0][tid] + part[1][tid];
        chN[b * HE + tid] = __float2half(ctxv);

        // p_copy
        float pp_ = sNxt[b * HD + tid] * copy_W[tid] + ctxv * copy_W[HD + tid];
        float tot = blockSum(pp_, red);
        if (tid == 0) pcT[b] = sigmoid_fast(tot + copy_b[0]);
    }
}

// ---------------------------------------------------------------------------
// Batched tail (per chunk of steps)
// ---------------------------------------------------------------------------
__global__ __launch_bounds__(256) void mred_all(
    const float* __restrict__ rv, const float* __restrict__ rvemb,
    const float* __restrict__ read_b, __half* __restrict__ mh)
{
    int idx = blockIdx.x * 256 + threadIdx.x;
    int row = idx >> 8, c = idx & 255;
    size_t o = (size_t)row * 512;
    float r0 = rv[o + 2 * c]     + rvemb[o + 2 * c]     + read_b[2 * c];
    float r1 = rv[o + 2 * c + 1] + rvemb[o + 2 * c + 1] + read_b[2 * c + 1];
    mh[idx] = __float2half(fmaxf(r0, r1));
}

__global__ __launch_bounds__(1024) void output_all(
    const float* __restrict__ energy,
    const float* __restrict__ attnb,
    const float* __restrict__ pcb,
    float* __restrict__ out, int row0)
{
    __shared__ float red[32];
    int row = row0 + blockIdx.x;          // t*128 + b
    int t = row >> 7, b = row & 127;
    int tid = threadIdx.x;
    const float4* eb4 = (const float4*)(energy + (size_t)row * VV);

    float mx = -INFINITY;
    for (int j = tid; j < VV / 4; j += 1024) {
        float4 v = eb4[j];
        mx = fmaxf(mx, fmaxf(fmaxf(v.x, v.y), fmaxf(v.z, v.w)));
    }
    mx = blockMax(mx, red);

    float sm = 0.0f;
    for (int j = tid; j < VV / 4; j += 1024) {
        float4 v = eb4[j];
        sm += __expf(v.x - mx) + __expf(v.y - mx) + __expf(v.z - mx) + __expf(v.w - mx);
    }
    sm = blockSum(sm, red);

    float pc = pcb[row];
    float scale = (1.0f - pc) / sm;
    float* ob = out + ((size_t)b * TT + t) * (VV + LL);
    float4* ob4 = (float4*)ob;
    for (int j = tid; j < VV / 4; j += 1024) {
        float4 v = eb4[j], o;
        o.x = __logf(__expf(v.x - mx) * scale + 1e-12f);
        o.y = __logf(__expf(v.y - mx) * scale + 1e-12f);
        o.z = __logf(__expf(v.z - mx) * scale + 1e-12f);
        o.w = __logf(__expf(v.w - mx) * scale + 1e-12f);
        ob4[j] = o;
    }
    const float4* at4 = (const float4*)(attnb + (size_t)row * LL);
    float4* oc4 = (float4*)(ob + VV);
    for (int j = tid; j < LL / 4; j += 1024) {
        float4 a = at4[j], o;
        o.x = __logf(fmaf(pc, a.x, 1e-12f));
        o.y = __logf(fmaf(pc, a.y, 1e-12f));
        o.z = __logf(fmaf(pc, a.z, 1e-12f));
        o.w = __logf(fmaf(pc, a.w, 1e-12f));
        oc4[j] = o;
    }
}

// ---------------------------------------------------------------------------
// Host orchestration
// ---------------------------------------------------------------------------
extern "C" void kernel_launch(void* const* d_in, const int* in_sizes, int n_in,
                              void* d_out, int out_size)
{
    const float* enc     = (const float*)d_in[0];
    const float* s_in    = (const float*)d_in[1];
    const int*   src     = (const int*)  d_in[2];
    const int*   tgt     = (const int*)  d_in[3];
    const float* embed   = (const float*)d_in[4];
    const float* W_ih    = (const float*)d_in[5];
    const float* b_ih    = (const float*)d_in[6];
    const float* W_hh    = (const float*)d_in[7];
    const float* b_hh    = (const float*)d_in[8];
    const float* att_Wh  = (const float*)d_in[9];
    const float* att_Ws  = (const float*)d_in[10];
    const float* att_b   = (const float*)d_in[11];
    const float* att_v   = (const float*)d_in[12];
    const float* copy_W  = (const float*)d_in[13];
    const float* copy_b  = (const float*)d_in[14];
    const float* read_W  = (const float*)d_in[15];
    const float* read_b  = (const float*)d_in[16];
    const float* read_Wo = (const float*)d_in[17];
    float* out = (float*)d_out;

    __half *p_ench, *p_projh, *p_embh, *p_Wihe, *p_Wre, *p_Wrc, *p_Wo;
    __half *p_Wh, *p_shh, *p_chh, *p_mh;
    float *p_giemb, *p_rvemb, *p_rv, *p_attn, *p_pc, *p_energy;

    cudaGetSymbolAddress((void**)&p_ench,  g_enc_h);
    cudaGetSymbolAddress((void**)&p_projh, g_proj_h);
    cudaGetSymbolAddress((void**)&p_embh,  g_embed_h);
    cudaGetSymbolAddress((void**)&p_Wihe,  g_Wih_e);
    cudaGetSymbolAddress((void**)&p_Wh,    g_Wh);
    cudaGetSymbolAddress((void**)&p_Wre,   g_Wr_e);
    cudaGetSymbolAddress((void**)&p_Wrc,   g_Wr_c);
    cudaGetSymbolAddress((void**)&p_Wo,    g_Wo);
    cudaGetSymbolAddress((void**)&p_giemb, g_giemb);
    cudaGetSymbolAddress((void**)&p_rvemb, g_rvemb);
    cudaGetSymbolAddress((void**)&p_shh,   g_shh);
    cudaGetSymbolAddress((void**)&p_chh,   g_chh);
    cudaGetSymbolAddress((void**)&p_attn,  g_attnb);
    cudaGetSymbolAddress((void**)&p_pc,    g_pcb);
    cudaGetSymbolAddress((void**)&p_rv,    g_rv_all);
    cudaGetSymbolAddress((void**)&p_mh,    g_mh_all);
    cudaGetSymbolAddress((void**)&p_energy,g_energy_all);

    cudaStream_t side;
    cudaStreamCreateWithFlags(&side, cudaStreamNonBlocking);
    cudaEvent_t evF, evJ;
    cudaEventCreateWithFlags(&evF, cudaEventDisableTiming);
    cudaEventCreateWithFlags(&evJ, cudaEventDisableTiming);

    // ---- Launch 0: ALL conversions + init ----
    {
        CvtArgs a{enc, embed, W_ih, W_hh, att_Ws, att_Wh, read_W, read_Wo, s_in};
        cvt_all<<<dim3(1024, 14), 256>>>(a);
    }

    // ---- Launch 1: ALL precompute GEMMs in one kernel ----
    {
        GH gp{}; gp.A = p_ench; gp.lda = HE; gp.W = p_Wh; gp.ldw = 512;
        gp.C = (float*)p_projh; gp.ldc = AA; gp.N = AA;
        gp.kbeg = 0; gp.kend = 512;
        GH ge{}; ge.embed = p_embh; ge.tgt = tgt; ge.W = p_Wihe; ge.ldw = 304;
        ge.C = p_giemb; ge.ldc = 1536; ge.N = 1536;
        ge.kbeg = 0; ge.kend = 304;
        GH gr{}; gr.embed = p_embh; gr.tgt = tgt; gr.W = p_Wre; gr.ldw = 304;
        gr.C = p_rvemb; gr.ldc = 512; gr.N = 512;
        gr.kbeg = 0; gr.kend = 304;
        k_uber<<<8320, 128, SMEM_GEMM>>>(gp, ge, gr);
    }

    // Tail-chunk launcher (stream st, steps [t0, t0+ns))
    auto tail_chunk = [&](cudaStream_t st, int t0, int ns) {
        int rows = ns * BB;
        {   // rv = [ctx, s] @ Wr_c^T
            GH g{}; g.ctx = p_chh + (size_t)(t0 + 1) * BB * HE;
            g.s = p_shh + (size_t)(t0 + 1) * BB * HD;
            g.W = p_Wrc; g.ldw = 1024;
            g.C = p_rv + (size_t)t0 * BB * 512; g.ldc = 512; g.N = 512;
            g.kbeg = 0; g.kend = 1024;
            k_g_cs<<<dim3(8, rows / 64), 128, SMEM_GEMM, st>>>(g);
        }
        mred_all<<<rows, 256, 0, st>>>(
            p_rv + (size_t)t0 * BB * 512,
            p_rvemb + (size_t)t0 * BB * 512,
            read_b, p_mh + (size_t)t0 * BB * 256);
        {   // energy = m @ read_Wo^T
            GH g{}; g.A = p_mh + (size_t)t0 * BB * 256; g.lda = 256;
            g.W = p_Wo; g.ldw = 256;
            g.C = p_energy + (size_t)t0 * BB * VV; g.ldc = VV; g.N = VV;
            g.kbeg = 0; g.kend = 256;
            k_g_plain<<<dim3(313, rows / 64), 128, SMEM_GEMM, st>>>(g);
        }
        output_all<<<rows, 1024, 0, st>>>(p_energy, p_attn, p_pc, out, t0 * BB);
    };

    // ---- Launches 2..31: the recurrence ----
    for (int t = 0; t < TT; t++) {
        step_kernel<<<272, 512, SMEM_STEP>>>(t, b_ih, b_hh, att_b, att_v,
                                             src, copy_W, copy_b);
        if (t == CH1 - 1) {
            // Fork tail chunk 1 (steps 0..CH1-1) onto the side stream
            cudaEventRecord(evF, 0);
            cudaStreamWaitEvent(side, evF, 0);
            tail_chunk(side, 0, CH1);
        }
    }

    // ---- Tail chunk 2 (steps CH1..TT-1) on stream 0 ----
    tail_chunk(0, CH1, TT - CH1);

    // ---- Join side stream ----
    cudaEventRecord(evJ, side);
    cudaStreamWaitEvent(0, evJ, 0);
}

// round 15
// speedup vs baseline: 1.2455x; 1.2455x over previous
#include <cuda_runtime.h>
#include <cuda_fp16.h>
#include <cstdint>
#include <cmath>

// Problem constants
#define BB   128
#define LL   400
#define TT   30
#define EE   300
#define HE   512
#define HD   512
#define AA   512
#define VV   20000
#define PAD_ID 0
#define UNK_ID 1
#define SOS_ID 2

#define STAGES 4
#define SK     40                      // smem row stride in halfs (32 + 8 pad)
#define SMEM_GEMM (2 * STAGES * 64 * SK * 2)   // 40960 bytes (64x64 tiles)
#define SMEM_STEP (2 * 2 * 128 * SK * 2)       // 40960 bytes (128x128, 2-stage)
#define CH1 15                         // tail chunk 1 = steps [0, CH1)

// ---------------------------------------------------------------------------
// Scratch (device globals)
// ---------------------------------------------------------------------------
__device__ __align__(256) __half g_enc_h [(size_t)BB * LL * HE];     // 52 MB
__device__ __align__(256) __half g_proj_h[(size_t)BB * LL * AA];     // 52 MB
__device__ __align__(256) __half g_embed_h[(size_t)VV * 304];        // 12 MB
__device__ __align__(256) __half g_Wih_e[1536 * 304];
__device__ __align__(256) __half g_Wih_c[1536 * 512];
__device__ __align__(256) __half g_Whh  [1536 * 512];
__device__ __align__(256) __half g_Ws   [512 * 512];
__device__ __align__(256) __half g_Wh   [512 * 512];
__device__ __align__(256) __half g_Wr_e [512 * 304];
__device__ __align__(256) __half g_Wr_c [512 * 1024];
__device__ __align__(256) __half g_Wo   [(size_t)VV * 256];
__device__ __align__(256) float  g_giemb[(size_t)TT * BB * 1536];    // 23.6 MB
__device__ __align__(256) float  g_rvemb[(size_t)TT * BB * 512];     // 7.9 MB
__device__ __align__(256) float  g_gi_p [4 * BB * 1536];
__device__ __align__(256) float  g_gh_p [4 * BB * 1536];
__device__ __align__(256) float  g_qp   [4 * BB * 512];
// Per-step ring buffers
__device__ __align__(256) float  g_sf  [(size_t)(TT + 1) * BB * HD];
__device__ __align__(256) __half g_shh [(size_t)(TT + 1) * BB * HD];
__device__ __align__(256) __half g_chh [(size_t)(TT + 1) * BB * HE];
__device__ __align__(256) float  g_attnb[(size_t)TT * BB * LL];
__device__ __align__(256) float  g_pcb  [TT * BB];
// Batched tail buffers
__device__ __align__(256) float  g_rv_all [(size_t)TT * BB * 512];   // 7.9 MB
__device__ __align__(256) __half g_mh_all [(size_t)TT * BB * 256];   // 2 MB
__device__ __align__(256) float  g_energy_all[(size_t)TT * BB * VV]; // 307 MB
// Phase counters: [0..TT) gates, [TT..2TT) gru, [2TT..3TT) q. Zeroed per call.
__device__ __align__(256) unsigned g_cnt[3 * TT];

// ---------------------------------------------------------------------------
// Low-level helpers
// ---------------------------------------------------------------------------
__device__ __forceinline__ void cp_async16(uint32_t dst, const void* src, int bytes) {
    asm volatile("cp.async.ca.shared.global [%0], [%1], 16, %2;\n"
                 :: "r"(dst), "l"(src), "r"(bytes));
}
__device__ __forceinline__ void cp_commit() {
    asm volatile("cp.async.commit_group;\n" ::: "memory");
}
template <int N>
__device__ __forceinline__ void cp_wait() {
    asm volatile("cp.async.wait_group %0;\n" :: "n"(N) : "memory");
}

__device__ __forceinline__ void ldsm4(uint32_t (&r)[4], uint32_t addr) {
    asm volatile("ldmatrix.sync.aligned.m8n8.x4.shared.b16 {%0,%1,%2,%3}, [%4];"
                 : "=r"(r[0]), "=r"(r[1]), "=r"(r[2]), "=r"(r[3]) : "r"(addr));
}

__device__ __forceinline__ void mma_f16(float (&c)[4], const uint32_t (&a)[4],
                                        uint32_t b0, uint32_t b1) {
    asm volatile(
        "mma.sync.aligned.m16n8k16.row.col.f32.f16.f16.f32 "
        "{%0,%1,%2,%3}, {%4,%5,%6,%7}, {%8,%9}, {%0,%1,%2,%3};\n"
        : "+f"(c[0]), "+f"(c[1]), "+f"(c[2]), "+f"(c[3])
        : "r"(a[0]), "r"(a[1]), "r"(a[2]), "r"(a[3]), "r"(b0), "r"(b1));
}

__device__ __forceinline__ unsigned ld_acq(const unsigned* p) {
    unsigned v;
    asm volatile("ld.acquire.gpu.global.u32 %0, [%1];"
                 : "=r"(v) : "l"(p) : "memory");
    return v;
}

// f16x2 ops for the attention scores phase
__device__ __forceinline__ uint32_t hadd2_(uint32_t a, uint32_t b) {
    uint32_t d;
    asm("add.f16x2 %0, %1, %2;" : "=r"(d) : "r"(a), "r"(b));
    return d;
}
__device__ __forceinline__ uint32_t hfma2_(uint32_t a, uint32_t b, uint32_t c) {
    uint32_t d;
    asm("fma.rn.f16x2 %0, %1, %2, %3;" : "=r"(d) : "r"(a), "r"(b), "r"(c));
    return d;
}
__device__ __forceinline__ uint32_t tanh2_(uint32_t x) {
    uint32_t d;
    asm("tanh.approx.f16x2 %0, %1;" : "=r"(d) : "r"(x));
    return d;
}

__device__ __forceinline__ float sigmoid_fast(float x) {
    return __fdividef(1.0f, 1.0f + __expf(-x));
}
__device__ __forceinline__ float tanh_fast(float x) {
    x = fminf(15.0f, fmaxf(-15.0f, x));
    float e = __expf(2.0f * x);
    return 1.0f - __fdividef(2.0f, e + 1.0f);
}

__device__ __forceinline__ float warpMax(float v) {
    #pragma unroll
    for (int o = 16; o; o >>= 1) v = fmaxf(v, __shfl_xor_sync(0xffffffffu, v, o));
    return v;
}
__device__ __forceinline__ float warpSum(float v) {
    #pragma unroll
    for (int o = 16; o; o >>= 1) v += __shfl_xor_sync(0xffffffffu, v, o);
    return v;
}
__device__ __forceinline__ float blockMax(float v, float* red) {
    v = warpMax(v);
    int w = threadIdx.x >> 5, l = threadIdx.x & 31, nw = blockDim.x >> 5;
    if (l == 0) red[w] = v;
    __syncthreads();
    if (threadIdx.x < 32) {
        float x = (threadIdx.x < nw) ? red[threadIdx.x] : -INFINITY;
        x = warpMax(x);
        if (threadIdx.x == 0) red[0] = x;
    }
    __syncthreads();
    v = red[0];
    __syncthreads();
    return v;
}
__device__ __forceinline__ float blockSum(float v, float* red) {
    v = warpSum(v);
    int w = threadIdx.x >> 5, l = threadIdx.x & 31, nw = blockDim.x >> 5;
    if (l == 0) red[w] = v;
    __syncthreads();
    if (threadIdx.x < 32) {
        float x = (threadIdx.x < nw) ? red[threadIdx.x] : 0.0f;
        x = warpSum(x);
        if (threadIdx.x == 0) red[0] = x;
    }
    __syncthreads();
    v = red[0];
    __syncthreads();
    return v;
}

// ---------------------------------------------------------------------------
// cvt_all: every fp32->fp16 repack + s copy + zeroing, in ONE launch.
// ---------------------------------------------------------------------------
struct CvtArgs {
    const float* enc;
    const float* embed;
    const float* W_ih;
    const float* W_hh;
    const float* att_Ws;
    const float* att_Wh;
    const float* read_W;
    const float* read_Wo;
    const float* s_in;
};

__device__ __forceinline__ void cvt_job(
    const float* __restrict__ src, __half* __restrict__ dst,
    int rows, int sstr, int soff, int dstr, int clen)
{
    int total = rows * dstr;
    for (int i = blockIdx.x * blockDim.x + threadIdx.x; i < total;
         i += gridDim.x * blockDim.x) {
        int r = i / dstr, c = i - r * dstr;
        float v = (c < clen) ? src[(size_t)r * sstr + soff + c] : 0.0f;
        dst[i] = __float2half(v);
    }
}

__global__ __launch_bounds__(256) void cvt_all(CvtArgs a) {
    switch (blockIdx.y) {
    case 0:  cvt_job(a.enc,     g_enc_h,   BB * LL, 512, 0, 512, 512); break;
    case 1:  cvt_job(a.embed,   g_embed_h, VV, 300, 0, 304, 300); break;
    case 2:  cvt_job(a.W_ih,    g_Wih_e,   1536, 812, 0, 304, 300); break;
    case 3:  cvt_job(a.W_ih,    g_Wih_c,   1536, 812, 300, 512, 512); break;
    case 4:  cvt_job(a.W_hh,    g_Whh,     1536, 512, 0, 512, 512); break;
    case 5:  cvt_job(a.att_Ws,  g_Ws,      512, 512, 0, 512, 512); break;
    case 6:  cvt_job(a.att_Wh,  g_Wh,      512, 512, 0, 512, 512); break;
    case 7:  cvt_job(a.read_W,  g_Wr_e,    512, 1324, 0, 304, 300); break;
    case 8:  cvt_job(a.read_W,  g_Wr_c,    512, 1324, 300, 1024, 1024); break;
    case 9:  cvt_job(a.read_Wo, g_Wo,      VV, 256, 0, 256, 256); break;
    case 10: cvt_job(a.s_in,    g_shh,     BB, 512, 0, 512, 512); break;
    case 11: {
        for (int i = blockIdx.x * blockDim.x + threadIdx.x; i < BB * HD;
             i += gridDim.x * blockDim.x)
            g_sf[i] = a.s_in[i];
        break;
    }
    case 12: {
        for (int i = blockIdx.x * blockDim.x + threadIdx.x; i < BB * HE;
             i += gridDim.x * blockDim.x)
            g_chh[i] = __float2half(0.0f);
        break;
    }
    default: {
        for (int i = blockIdx.x * blockDim.x + threadIdx.x; i < 3 * TT;
             i += gridDim.x * blockDim.x)
            g_cnt[i] = 0u;
        break;
    }
    }
}

// ---------------------------------------------------------------------------
// 64x64-tile fp16 GEMM (128 threads), explicit tile coords
// ---------------------------------------------------------------------------
struct GH {
    const __half* A; int lda;
    const __half* W; int ldw;
    float* C; int ldc;
    int N;
    int kbeg, kend;
    const __half* embed;
    const int*    tgt;
    const __half* ctx;
    const __half* s;
};

#define MODE_PLAIN 0
#define MODE_EMB   1
#define MODE_CS    2

template <int MODE, bool OUTH>
__device__ __forceinline__ void grun(const GH& g, int mt0, int nt0) {
    extern __shared__ __half smh[];
    __half* As = smh;
    __half* Ws = smh + STAGES * 64 * SK;

    const int tid = threadIdx.x, lane = tid & 31, warp = tid >> 5;
    const int wm = warp >> 1, wn = warp & 1;

    const int r0 = tid >> 2, kc = (tid & 3) * 8;
    const int r1 = r0 + 32;
    const int gm0 = mt0 + r0, gm1 = mt0 + r1;
    const int gn0 = nt0 + r0, gn1 = nt0 + r1;

    const __half *a0 = nullptr, *a1 = nullptr;
    const __half *c0p = nullptr, *c1p = nullptr, *s0p = nullptr, *s1p = nullptr;
    if (MODE == MODE_PLAIN) {
        a0 = g.A + (size_t)gm0 * g.lda;
        a1 = g.A + (size_t)gm1 * g.lda;
    } else if (MODE == MODE_EMB) {
        int t0 = gm0 >> 7, b0 = gm0 & 127;
        int w0 = (t0 == 0) ? SOS_ID : g.tgt[b0 * TT + t0 - 1];
        if (w0 >= VV) w0 = UNK_ID;
        int t1 = gm1 >> 7, b1 = gm1 & 127;
        int w1 = (t1 == 0) ? SOS_ID : g.tgt[b1 * TT + t1 - 1];
        if (w1 >= VV) w1 = UNK_ID;
        a0 = g.embed + (size_t)w0 * 304;
        a1 = g.embed + (size_t)w1 * 304;
    } else {
        c0p = g.ctx + (size_t)gm0 * 512; c1p = g.ctx + (size_t)gm1 * 512;
        s0p = g.s   + (size_t)gm0 * 512; s1p = g.s   + (size_t)gm1 * 512;
    }
    const bool n0ok = (gn0 < g.N), n1ok = (gn1 < g.N);
    const __half* w0p = g.W + (size_t)(n0ok ? gn0 : 0) * g.ldw;
    const __half* w1p = g.W + (size_t)(n1ok ? gn1 : 0) * g.ldw;

    const uint32_t asB = (uint32_t)__cvta_generic_to_shared(As);
    const uint32_t wsB = (uint32_t)__cvta_generic_to_shared(Ws);
    const int STB = 64 * SK * 2;
    const uint32_t aD0 = asB + (r0 * SK + kc) * 2;
    const uint32_t aD1 = asB + (r1 * SK + kc) * 2;
    const uint32_t wD0 = wsB + (r0 * SK + kc) * 2;
    const uint32_t wD1 = wsB + (r1 * SK + kc) * 2;

    const int nk = (g.kend - g.kbeg + 31) >> 5;

    auto pf = [&](int i) {
        int kg = g.kbeg + i * 32 + kc;
        int buf = (i & 3) * STB;
        bool v = kg < g.kend;
        const __half *sa0, *sa1;
        if (MODE == MODE_CS) {
            sa0 = (kg < 512) ? c0p + kg : s0p + (kg - 512);
            sa1 = (kg < 512) ? c1p + kg : s1p + (kg - 512);
        } else {
            sa0 = a0 + kg; sa1 = a1 + kg;
        }
        if (!v) { sa0 = g.W; sa1 = g.W; }
        cp_async16(aD0 + buf, sa0, v ? 16 : 0);
        cp_async16(aD1 + buf, sa1, v ? 16 : 0);
        bool v0 = v && n0ok, v1 = v && n1ok;
        cp_async16(wD0 + buf, v0 ? (w0p + kg) : g.W, v0 ? 16 : 0);
        cp_async16(wD1 + buf, v1 ? (w1p + kg) : g.W, v1 ? 16 : 0);
    };

    #pragma unroll
    for (int p = 0; p < 3; p++) {
        if (p < nk) pf(p);
        cp_commit();
    }

    float c[2][4][4] = {};
    const int lr = lane & 15, lk = (lane >> 4) * 8;

    for (int i = 0; i < nk; i++) {
        if (i + 3 < nk) pf(i + 3);
        cp_commit();
        cp_wait<3>();
        __syncthreads();

        const uint32_t ab = asB + (i & 3) * STB;
        const uint32_t wb = wsB + (i & 3) * STB;

        #pragma unroll
        for (int kk = 0; kk < 32; kk += 16) {
            uint32_t a[2][4], bb[2][4];
            #pragma unroll
            for (int mt = 0; mt < 2; mt++)
                ldsm4(a[mt], ab + ((wm * 32 + mt * 16 + lr) * SK + kk + lk) * 2);
            #pragma unroll
            for (int n2 = 0; n2 < 2; n2++)
                ldsm4(bb[n2], wb + ((wn * 32 + n2 * 16 + lr) * SK + kk + lk) * 2);
            #pragma unroll
            for (int mt = 0; mt < 2; mt++)
                #pragma unroll
                for (int ns = 0; ns < 4; ns++) {
                    int n2 = ns >> 1, sel = ns & 1;
                    mma_f16(c[mt][ns], a[mt], bb[n2][sel], bb[n2][sel + 2]);
                }
        }
        __syncthreads();
    }

    const int gr = lane >> 2, gc = (lane & 3) * 2;
    #pragma unroll
    for (int mt = 0; mt < 2; mt++)
        #pragma unroll
        for (int ns = 0; ns < 4; ns++) {
            int row = mt0 + wm * 32 + mt * 16 + gr;
            int col = nt0 + wn * 32 + ns * 8 + gc;
            if (col < g.N) {
                if (OUTH) {
                    __half* Ch = (__half*)g.C;
                    Ch[(size_t)row * g.ldc + col]           = __float2half(c[mt][ns][0]);
                    Ch[(size_t)row * g.ldc + col + 1]       = __float2half(c[mt][ns][1]);
                    Ch[(size_t)(row + 8) * g.ldc + col]     = __float2half(c[mt][ns][2]);
                    Ch[(size_t)(row + 8) * g.ldc + col + 1] = __float2half(c[mt][ns][3]);
                } else {
                    g.C[(size_t)row * g.ldc + col]           = c[mt][ns][0];
                    g.C[(size_t)row * g.ldc + col + 1]       = c[mt][ns][1];
                    g.C[(size_t)(row + 8) * g.ldc + col]     = c[mt][ns][2];
                    g.C[(size_t)(row + 8) * g.ldc + col + 1] = c[mt][ns][3];
                }
            }
        }
}

__global__ __launch_bounds__(128) void k_g_plain(GH g) {
    grun<MODE_PLAIN, false>(g, blockIdx.y * 64, blockIdx.x * 64);
}
__global__ __launch_bounds__(128) void k_g_cs(GH g) {
    grun<MODE_CS, false>(g, blockIdx.y * 64, blockIdx.x * 64);
}

// All three precompute GEMMs in ONE launch (flattened grid)
__global__ __launch_bounds__(128) void k_uber(GH gp, GH ge, GH gr) {
    int bid = blockIdx.x;
    if (bid < 6400) {           // proj: 8 x 800 tiles
        grun<MODE_PLAIN, true>(gp, (bid / 8) * 64, (bid % 8) * 64);
    } else if (bid < 7840) {    // giemb: 24 x 60 tiles
        int j = bid - 6400;
        grun<MODE_EMB, false>(ge, (j / 24) * 64, (j % 24) * 64);
    } else {                    // rvemb: 8 x 60 tiles
        int j = bid - 7840;
        grun<MODE_EMB, false>(gr, (j / 8) * 64, (j % 8) * 64);
    }
}

// ---------------------------------------------------------------------------
// 128x128-tile fp16 GEMM (512 threads, 2-stage) — used inside step_kernel.
// ---------------------------------------------------------------------------
__device__ __forceinline__ void grun512(
    const __half* __restrict__ A, int lda,
    const __half* __restrict__ W, int ldw,
    float* __restrict__ C, int ldc, int N,
    int kbeg, int kend, int nt0)
{
    extern __shared__ __half smh[];
    __half* As = smh;
    __half* Ws = smh + 2 * 128 * SK;

    const int tid = threadIdx.x, lane = tid & 31, warp = tid >> 5;
    const int wm = warp >> 2, wn = warp & 3;

    const int r = tid >> 2, kc = (tid & 3) * 8;
    const __half* aRow = A + (size_t)r * lda;
    const int gn = nt0 + r;
    const bool nok = (gn < N);
    const __half* wRow = W + (size_t)(nok ? gn : 0) * ldw;

    const uint32_t asB = (uint32_t)__cvta_generic_to_shared(As);
    const uint32_t wsB = (uint32_t)__cvta_generic_to_shared(Ws);
    const int STB = 128 * SK * 2;
    const uint32_t aD = asB + (r * SK + kc) * 2;
    const uint32_t wD = wsB + (r * SK + kc) * 2;

    const int nk = (kend - kbeg + 31) >> 5;

    auto pf = [&](int i) {
        int kg = kbeg + i * 32 + kc;
        int buf = (i & 1) * STB;
        bool v = kg < kend;
        cp_async16(aD + buf, v ? (const void*)(aRow + kg) : (const void*)W,
                   v ? 16 : 0);
        bool vw = v && nok;
        cp_async16(wD + buf, vw ? (const void*)(wRow + kg) : (const void*)W,
                   vw ? 16 : 0);
    };

    pf(0);
    cp_commit();

    float c[2][4][4] = {};
    const int lr = lane & 15, lk = (lane >> 4) * 8;

    for (int i = 0; i < nk; i++) {
        if (i + 1 < nk) pf(i + 1);
        cp_commit();
        cp_wait<1>();
        __syncthreads();

        const uint32_t ab = asB + (i & 1) * STB;
        const uint32_t wb = wsB + (i & 1) * STB;

        #pragma unroll
        for (int kk = 0; kk < 32; kk += 16) {
            uint32_t a[2][4], bb[2][4];
            #pragma unroll
            for (int mt = 0; mt < 2; mt++)
                ldsm4(a[mt], ab + ((wm * 32 + mt * 16 + lr) * SK + kk + lk) * 2);
            #pragma unroll
            for (int n2 = 0; n2 < 2; n2++)
                ldsm4(bb[n2], wb + ((wn * 32 + n2 * 16 + lr) * SK + kk + lk) * 2);
            #pragma unroll
            for (int mt = 0; mt < 2; mt++)
                #pragma unroll
                for (int ns = 0; ns < 4; ns++) {
                    int n2 = ns >> 1, sel = ns & 1;
                    mma_f16(c[mt][ns], a[mt], bb[n2][sel], bb[n2][sel + 2]);
                }
        }
        __syncthreads();
    }

    const int gr = lane >> 2, gc = (lane & 3) * 2;
    #pragma unroll
    for (int mt = 0; mt < 2; mt++)
        #pragma unroll
        for (int ns = 0; ns < 4; ns++) {
            int row = wm * 32 + mt * 16 + gr;
            int col = nt0 + wn * 32 + ns * 8 + gc;
            if (col < N) {
                C[(size_t)row * ldc + col]           = c[mt][ns][0];
                C[(size_t)row * ldc + col + 1]       = c[mt][ns][1];
                C[(size_t)(row + 8) * ldc + col]     = c[mt][ns][2];
                C[(size_t)(row + 8) * ldc + col + 1] = c[mt][ns][3];
            }
        }
}

// ---------------------------------------------------------------------------
// step_kernel: all 4 phases of one decoder step in one launch.
// bid 0..95 gates | 96..127 gru | 128..143 q | 144..271 attention
// ---------------------------------------------------------------------------
__global__ __launch_bounds__(512) void step_kernel(
    int t,
    const float* __restrict__ b_ih, const float* __restrict__ b_hh,
    const float* __restrict__ att_b, const float* __restrict__ vvec,
    const int*   __restrict__ src,
    const float* __restrict__ copy_W, const float* __restrict__ copy_b)
{
    __shared__ __align__(16) float es[LL];
    __shared__ float red[32];

    const int bid = blockIdx.x, tid = threadIdx.x;
    const __half* shC = g_shh + (size_t)t * BB * HD;
    __half*       shN = g_shh + (size_t)(t + 1) * BB * HD;
    const __half* chC = g_chh + (size_t)t * BB * HE;
    __half*       chN = g_chh + (size_t)(t + 1) * BB * HE;
    const float*  sCur = g_sf + (size_t)t * BB * HD;
    float*        sNxt = g_sf + (size_t)(t + 1) * BB * HD;

    if (bid < 96) {
        // ---- Phase A: gates GEMMs ----
        int half = bid / 48, j = bid % 48;
        int sp = j / 12, nt = j % 12;
        const __half* A = half ? shC : chC;
        const __half* W = half ? g_Whh : g_Wih_c;
        float* C = (half ? g_gh_p : g_gi_p) + (size_t)sp * BB * 1536;
        grun512(A, 512, W, 512, C, 1536, 1536, sp * 128, sp * 128 + 128,
                nt * 128);
        __threadfence();
        __syncthreads();
        if (tid == 0) atomicAdd(&g_cnt[t], 1u);
    } else if (bid < 128) {
        // ---- Phase B: GRU ----
        if (tid == 0) {
            while (ld_acq(&g_cnt[t]) < 96u) __nanosleep(64);
        }
        __syncthreads();
        for (int i = (bid - 96) * 512 + tid; i < BB * HD; i += 32 * 512) {
            int b = i >> 9, h = i & 511;
            size_t ob = (size_t)b * 1536;
            size_t oe = ((size_t)t * BB + b) * 1536;
            float ir = g_giemb[oe + h]        + b_ih[h];
            float iz = g_giemb[oe + 512 + h]  + b_ih[512 + h];
            float in = g_giemb[oe + 1024 + h] + b_ih[1024 + h];
            float hr = b_hh[h], hz = b_hh[512 + h], hn = b_hh[1024 + h];
            #pragma unroll
            for (int z = 0; z < 4; z++) {
                size_t o = (size_t)z * BB * 1536 + ob;
                ir += g_gi_p[o + h];        iz += g_gi_p[o + 512 + h];
                in += g_gi_p[o + 1024 + h];
                hr += g_gh_p[o + h];        hz += g_gh_p[o + 512 + h];
                hn += g_gh_p[o + 1024 + h];
            }
            float r = sigmoid_fast(ir + hr);
            float z = sigmoid_fast(iz + hz);
            float n = tanh_fast(in + r * hn);
            float sn = (1.0f - z) * n + z * sCur[i];
            sNxt[i] = sn;
            shN[i] = __float2half(sn);
        }
        __threadfence();
        __syncthreads();
        if (tid == 0) atomicAdd(&g_cnt[TT + t], 1u);
    } else if (bid < 144) {
        // ---- Phase C: q split-K4 GEMM ----
        if (tid == 0) {
            while (ld_acq(&g_cnt[TT + t]) < 32u) __nanosleep(64);
        }
        __syncthreads();
        int j = bid - 128, sp = j >> 2, nt = j & 3;
        grun512(shN, 512, g_Ws, 512, g_qp + (size_t)sp * BB * 512, 512, 512,
                sp * 128, sp * 128 + 128, nt * 128);
        __threadfence();
        __syncthreads();
        if (tid == 0) atomicAdd(&g_cnt[2 * TT + t], 1u);
    } else {
        // ---- Phase D: attention (deep-MLP scores + uint4 ctx) ----
        extern __shared__ __half smh[];
        float* part = (float*)smh;              // [8][512] fp32 = 16 KB
        int b = bid - 144;
        if (tid == 0) {
            while (ld_acq(&g_cnt[2 * TT + t]) < 16u) __nanosleep(64);
        }
        __syncthreads();

        int warp = tid >> 5, lane = tid & 31;
        float* atT = g_attnb + (size_t)t * BB * LL;
        float* pcT = g_pcb + (size_t)t * BB;

        // q (bias + 4 partials) and v as half2 registers
        uint32_t qh[2][4], vh[2][4];
        #pragma unroll
        for (int j = 0; j < 2; j++) {
            int base = (lane + 32 * j) * 8;
            float qf[8];
            #pragma unroll
            for (int p = 0; p < 8; p++) qf[p] = att_b[base + p];
            #pragma unroll
            for (int z = 0; z < 4; z++) {
                const float* qz = g_qp + ((size_t)z * BB + b) * 512 + base;
                float4 q0 = *(const float4*)qz;
                float4 q1 = *(const float4*)(qz + 4);
                qf[0] += q0.x; qf[1] += q0.y; qf[2] += q0.z; qf[3] += q0.w;
                qf[4] += q1.x; qf[5] += q1.y; qf[6] += q1.z; qf[7] += q1.w;
            }
            #pragma unroll
            for (int p = 0; p < 4; p++) {
                __half2 h = __floats2half2_rn(qf[2 * p], qf[2 * p + 1]);
                qh[j][p] = *(uint32_t*)&h;
                __half2 vv2 = __floats2half2_rn(vvec[base + 2 * p],
                                                vvec[base + 2 * p + 1]);
                vh[j][p] = *(uint32_t*)&vv2;
            }
        }

        // scores: warp owns rows [warp*25, warp*25+25); 4-row chunks with all
        // 8 uint4 loads issued before compute (deep MLP).
        auto scoreRow = [&](const uint4& va, const uint4& vb) -> float {
            const uint32_t* ha = (const uint32_t*)&va;
            const uint32_t* hb = (const uint32_t*)&vb;
            uint32_t acc0 = 0u, acc1 = 0u;
            #pragma unroll
            for (int p = 0; p < 4; p++) {
                acc0 = hfma2_(tanh2_(hadd2_(ha[p], qh[0][p])), vh[0][p], acc0);
                acc1 = hfma2_(tanh2_(hadd2_(hb[p], qh[1][p])), vh[1][p], acc1);
            }
            float2 f0 = __half22float2(*(__half2*)&acc0);
            float2 f1 = __half22float2(*(__half2*)&acc1);
            return (f0.x + f0.y) + (f1.x + f1.y);
        };

        const uint4* pb = (const uint4*)(g_proj_h + (size_t)b * LL * AA);
        const int r0w = warp * 25;
        #pragma unroll 1
        for (int c = 0; c < 6; c++) {
            int l = r0w + c * 4;
            uint4 a0 = pb[(size_t)(l + 0) * 64 + lane];
            uint4 b0 = pb[(size_t)(l + 0) * 64 + 32 + lane];
            uint4 a1 = pb[(size_t)(l + 1) * 64 + lane];
            uint4 b1 = pb[(size_t)(l + 1) * 64 + 32 + lane];
            uint4 a2 = pb[(size_t)(l + 2) * 64 + lane];
            uint4 b2 = pb[(size_t)(l + 2) * 64 + 32 + lane];
            uint4 a3 = pb[(size_t)(l + 3) * 64 + lane];
            uint4 b3 = pb[(size_t)(l + 3) * 64 + 32 + lane];
            float s0 = scoreRow(a0, b0);
            float s1 = scoreRow(a1, b1);
            float s2 = scoreRow(a2, b2);
            float s3 = scoreRow(a3, b3);
            s0 = warpSum(s0); s1 = warpSum(s1);
            s2 = warpSum(s2); s3 = warpSum(s3);
            if (lane == 0) {
                es[l]     = s0;
                es[l + 1] = s1;
                es[l + 2] = s2;
                es[l + 3] = s3;
            }
        }
        {   // final row (r0w + 24)
            int l = r0w + 24;
            uint4 a0 = pb[(size_t)l * 64 + lane];
            uint4 b0 = pb[(size_t)l * 64 + 32 + lane];
            float s0 = warpSum(scoreRow(a0, b0));
            if (lane == 0) es[l] = s0;
        }
        __syncthreads();

        // softmax over L (pad mask applied here, coalesced src read)
        float ev = -INFINITY;
        if (tid < LL)
            ev = (src[b * LL + tid] == PAD_ID) ? -1e30f : es[tid];
        float m  = blockMax(ev, red);
        float p  = (tid < LL) ? __expf(ev - m) : 0.0f;
        float Z  = blockSum(p, red);
        float a  = p / Z;
        if (tid < LL) { es[tid] = a; atT[b * LL + tid] = a; }
        __syncthreads();

        // ctx: uint4 loads; 8 groups x 64 threads; thread owns 8 columns
        int gg = tid >> 6, cc = tid & 63;
        const uint4* eb = (const uint4*)(g_enc_h + (size_t)b * LL * HE) + cc;
        float acc[8] = {};
        int l0 = gg * 50;
        #pragma unroll 2
        for (int l = l0; l < l0 + 50; l++) {
            uint4 v = eb[(size_t)l * 64];
            float w = es[l];
            const __half2* h = (const __half2*)&v;
            #pragma unroll
            for (int p = 0; p < 4; p++) {
                float2 f = __half22float2(h[p]);
                acc[2 * p]     += w * f.x;
                acc[2 * p + 1] += w * f.y;
            }
        }
        #pragma unroll
        for (int p = 0; p < 8; p++)
            part[gg * 512 + cc * 8 + p] = acc[p];
        __syncthreads();

        float ctxv = 0.0f;
        #pragma unroll
        for (int g2 = 0; g2 < 8; g2++)
            ctxv += part[g2 * 512 + tid];
        chN[b * HE + tid] = __float2half(ctxv);

        // p_copy
        float pp_ = sNxt[b * HD + tid] * copy_W[tid] + ctxv * copy_W[HD + tid];
        float tot = blockSum(pp_, red);
        if (tid == 0) pcT[b] = sigmoid_fast(tot + copy_b[0]);
    }
}

// ---------------------------------------------------------------------------
// Batched tail (per chunk of steps)
// ---------------------------------------------------------------------------
__global__ __launch_bounds__(256) void mred_all(
    const float* __restrict__ rv, const float* __restrict__ rvemb,
    const float* __restrict__ read_b, __half* __restrict__ mh)
{
    int idx = blockIdx.x * 256 + threadIdx.x;
    int row = idx >> 8, c = idx & 255;
    size_t o = (size_t)row * 512;
    float r0 = rv[o + 2 * c]     + rvemb[o + 2 * c]     + read_b[2 * c];
    float r1 = rv[o + 2 * c + 1] + rvemb[o + 2 * c + 1] + read_b[2 * c + 1];
    mh[idx] = __float2half(fmaxf(r0, r1));
}

__global__ __launch_bounds__(1024) void output_all(
    const float* __restrict__ energy,
    const float* __restrict__ attnb,
    const float* __restrict__ pcb,
    float* __restrict__ out, int row0)
{
    __shared__ float red[32];
    int row = row0 + blockIdx.x;          // t*128 + b
    int t = row >> 7, b = row & 127;
    int tid = threadIdx.x;
    const float4* eb4 = (const float4*)(energy + (size_t)row * VV);

    float mx = -INFINITY;
    for (int j = tid; j < VV / 4; j += 1024) {
        float4 v = eb4[j];
        mx = fmaxf(mx, fmaxf(fmaxf(v.x, v.y), fmaxf(v.z, v.w)));
    }
    mx = blockMax(mx, red);

    float sm = 0.0f;
    for (int j = tid; j < VV / 4; j += 1024) {
        float4 v = eb4[j];
        sm += __expf(v.x - mx) + __expf(v.y - mx) + __expf(v.z - mx) + __expf(v.w - mx);
    }
    sm = blockSum(sm, red);

    float pc = pcb[row];
    float scale = (1.0f - pc) / sm;
    float* ob = out + ((size_t)b * TT + t) * (VV + LL);
    float4* ob4 = (float4*)ob;
    for (int j = tid; j < VV / 4; j += 1024) {
        float4 v = eb4[j], o;
        o.x = __logf(__expf(v.x - mx) * scale + 1e-12f);
        o.y = __logf(__expf(v.y - mx) * scale + 1e-12f);
        o.z = __logf(__expf(v.z - mx) * scale + 1e-12f);
        o.w = __logf(__expf(v.w - mx) * scale + 1e-12f);
        ob4[j] = o;
    }
    const float4* at4 = (const float4*)(attnb + (size_t)row * LL);
    float4* oc4 = (float4*)(ob + VV);
    for (int j = tid; j < LL / 4; j += 1024) {
        float4 a = at4[j], o;
        o.x = __logf(fmaf(pc, a.x, 1e-12f));
        o.y = __logf(fmaf(pc, a.y, 1e-12f));
        o.z = __logf(fmaf(pc, a.z, 1e-12f));
        o.w = __logf(fmaf(pc, a.w, 1e-12f));
        oc4[j] = o;
    }
}

// ---------------------------------------------------------------------------
// Host orchestration
// ---------------------------------------------------------------------------
extern "C" void kernel_launch(void* const* d_in, const int* in_sizes, int n_in,
                              void* d_out, int out_size)
{
    const float* enc     = (const float*)d_in[0];
    const float* s_in    = (const float*)d_in[1];
    const int*   src     = (const int*)  d_in[2];
    const int*   tgt     = (const int*)  d_in[3];
    const float* embed   = (const float*)d_in[4];
    const float* W_ih    = (const float*)d_in[5];
    const float* b_ih    = (const float*)d_in[6];
    const float* W_hh    = (const float*)d_in[7];
    const float* b_hh    = (const float*)d_in[8];
    const float* att_Wh  = (const float*)d_in[9];
    const float* att_Ws  = (const float*)d_in[10];
    const float* att_b   = (const float*)d_in[11];
    const float* att_v   = (const float*)d_in[12];
    const float* copy_W  = (const float*)d_in[13];
    const float* copy_b  = (const float*)d_in[14];
    const float* read_W  = (const float*)d_in[15];
    const float* read_b  = (const float*)d_in[16];
    const float* read_Wo = (const float*)d_in[17];
    float* out = (float*)d_out;

    __half *p_ench, *p_projh, *p_embh, *p_Wihe, *p_Wre, *p_Wrc, *p_Wo;
    __half *p_Wh, *p_shh, *p_chh, *p_mh;
    float *p_giemb, *p_rvemb, *p_rv, *p_attn, *p_pc, *p_energy;

    cudaGetSymbolAddress((void**)&p_ench,  g_enc_h);
    cudaGetSymbolAddress((void**)&p_projh, g_proj_h);
    cudaGetSymbolAddress((void**)&p_embh,  g_embed_h);
    cudaGetSymbolAddress((void**)&p_Wihe,  g_Wih_e);
    cudaGetSymbolAddress((void**)&p_Wh,    g_Wh);
    cudaGetSymbolAddress((void**)&p_Wre,   g_Wr_e);
    cudaGetSymbolAddress((void**)&p_Wrc,   g_Wr_c);
    cudaGetSymbolAddress((void**)&p_Wo,    g_Wo);
    cudaGetSymbolAddress((void**)&p_giemb, g_giemb);
    cudaGetSymbolAddress((void**)&p_rvemb, g_rvemb);
    cudaGetSymbolAddress((void**)&p_shh,   g_shh);
    cudaGetSymbolAddress((void**)&p_chh,   g_chh);
    cudaGetSymbolAddress((void**)&p_attn,  g_attnb);
    cudaGetSymbolAddress((void**)&p_pc,    g_pcb);
    cudaGetSymbolAddress((void**)&p_rv,    g_rv_all);
    cudaGetSymbolAddress((void**)&p_mh,    g_mh_all);
    cudaGetSymbolAddress((void**)&p_energy,g_energy_all);

    cudaStream_t side;
    cudaStreamCreateWithFlags(&side, cudaStreamNonBlocking);
    cudaEvent_t evF, evJ;
    cudaEventCreateWithFlags(&evF, cudaEventDisableTiming);
    cudaEventCreateWithFlags(&evJ, cudaEventDisableTiming);

    // ---- Launch 0: ALL conversions + init ----
    {
        CvtArgs a{enc, embed, W_ih, W_hh, att_Ws, att_Wh, read_W, read_Wo, s_in};
        cvt_all<<<dim3(1024, 14), 256>>>(a);
    }

    // ---- Launch 1: ALL precompute GEMMs in one kernel ----
    {
        GH gp{}; gp.A = p_ench; gp.lda = HE; gp.W = p_Wh; gp.ldw = 512;
        gp.C = (float*)p_projh; gp.ldc = AA; gp.N = AA;
        gp.kbeg = 0; gp.kend = 512;
        GH ge{}; ge.embed = p_embh; ge.tgt = tgt; ge.W = p_Wihe; ge.ldw = 304;
        ge.C = p_giemb; ge.ldc = 1536; ge.N = 1536;
        ge.kbeg = 0; ge.kend = 304;
        GH gr{}; gr.embed = p_embh; gr.tgt = tgt; gr.W = p_Wre; gr.ldw = 304;
        gr.C = p_rvemb; gr.ldc = 512; gr.N = 512;
        gr.kbeg = 0; gr.kend = 304;
        k_uber<<<8320, 128, SMEM_GEMM>>>(gp, ge, gr);
    }

    // Tail-chunk launcher (stream st, steps [t0, t0+ns))
    auto tail_chunk = [&](cudaStream_t st, int t0, int ns) {
        int rows = ns * BB;
        {   // rv = [ctx, s] @ Wr_c^T
            GH g{}; g.ctx = p_chh + (size_t)(t0 + 1) * BB * HE;
            g.s = p_shh + (size_t)(t0 + 1) * BB * HD;
            g.W = p_Wrc; g.ldw = 1024;
            g.C = p_rv + (size_t)t0 * BB * 512; g.ldc = 512; g.N = 512;
            g.kbeg = 0; g.kend = 1024;
            k_g_cs<<<dim3(8, rows / 64), 128, SMEM_GEMM, st>>>(g);
        }
        mred_all<<<rows, 256, 0, st>>>(
            p_rv + (size_t)t0 * BB * 512,
            p_rvemb + (size_t)t0 * BB * 512,
            read_b, p_mh + (size_t)t0 * BB * 256);
        {   // energy = m @ read_Wo^T
            GH g{}; g.A = p_mh + (size_t)t0 * BB * 256; g.lda = 256;
            g.W = p_Wo; g.ldw = 256;
            g.C = p_energy + (size_t)t0 * BB * VV; g.ldc = VV; g.N = VV;
            g.kbeg = 0; g.kend = 256;
            k_g_plain<<<dim3(313, rows / 64), 128, SMEM_GEMM, st>>>(g);
        }
        output_all<<<rows, 1024, 0, st>>>(p_energy, p_attn, p_pc, out, t0 * BB);
    };

    // ---- Launches 2..31: the recurrence ----
    for (int t = 0; t < TT; t++) {
        step_kernel<<<272, 512, SMEM_STEP>>>(t, b_ih, b_hh, att_b, att_v,
                                             src, copy_W, copy_b);
        if (t == CH1 - 1) {
            cudaEventRecord(evF, 0);
            cudaStreamWaitEvent(side, evF, 0);
            tail_chunk(side, 0, CH1);
        }
    }

    // ---- Tail chunk 2 (steps CH1..TT-1) on stream 0 ----
    tail_chunk(0, CH1, TT - CH1);

    // ---- Join side stream ----
    cudaEventRecord(evJ, side);
    cudaStreamWaitEvent(0, evJ, 0);
}

// round 17
// speedup vs baseline: 1.3353x; 1.0721x over previous
#include <cuda_runtime.h>
#include <cuda_fp16.h>
#include <cstdint>
#include <cmath>

// Problem constants
#define BB   128
#define LL   400
#define TT   30
#define EE   300
#define HE   512
#define HD   512
#define AA   512
#define VV   20000
#define PAD_ID 0
#define UNK_ID 1
#define SOS_ID 2

#define STAGES 4
#define SK     40                      // smem row stride in halfs (32 + 8 pad)
#define SMEM_GEMM (2 * STAGES * 64 * SK * 2)   // 40960 bytes (64x64 tiles)
#define SMEM_STEP (2 * 2 * 128 * SK * 2)       // 40960 bytes (128x128, 2-stage)
#define CH1 15                         // tail chunk 1 = steps [0, CH1)

// ---------------------------------------------------------------------------
// Scratch (device globals)
// ---------------------------------------------------------------------------
__device__ __align__(256) __half g_enc_h [(size_t)BB * LL * HE];     // 52 MB
__device__ __align__(256) __half g_proj_h[(size_t)BB * LL * AA];     // 52 MB
__device__ __align__(256) __half g_embed_h[(size_t)VV * 304];        // 12 MB
__device__ __align__(256) __half g_Wih_e[1536 * 304];
__device__ __align__(256) __half g_Wih_c[1536 * 512];
__device__ __align__(256) __half g_Whh  [1536 * 512];
__device__ __align__(256) __half g_Ws   [512 * 512];
__device__ __align__(256) __half g_Wh   [512 * 512];
__device__ __align__(256) __half g_Wr_e [512 * 304];
__device__ __align__(256) __half g_Wr_c [512 * 1024];
__device__ __align__(256) __half g_Wo   [(size_t)VV * 256];
__device__ __align__(256) float  g_giemb[(size_t)TT * BB * 1536];    // 23.6 MB
__device__ __align__(256) float  g_rvemb[(size_t)TT * BB * 512];     // 7.9 MB
__device__ __align__(256) float  g_gi_p [4 * BB * 1536];
__device__ __align__(256) float  g_gh_p [4 * BB * 1536];
__device__ __align__(256) float  g_qp   [4 * BB * 512];
// Per-step ring buffers
__device__ __align__(256) float  g_sf  [(size_t)(TT + 1) * BB * HD];
__device__ __align__(256) __half g_shh [(size_t)(TT + 1) * BB * HD];
__device__ __align__(256) __half g_chh [(size_t)(TT + 1) * BB * HE];
__device__ __align__(256) float  g_attnb[(size_t)TT * BB * LL];
__device__ __align__(256) float  g_pcb  [TT * BB];
// Batched tail buffers
__device__ __align__(256) float  g_rv_all [(size_t)TT * BB * 512];   // 7.9 MB
__device__ __align__(256) __half g_mh_all [(size_t)TT * BB * 256];   // 2 MB
__device__ __align__(256) float  g_energy_all[(size_t)TT * BB * VV]; // 307 MB
// Phase counters: [0..TT) gates, [TT..2TT) gru, [2TT..3TT) q. Zeroed per call.
__device__ __align__(256) unsigned g_cnt[3 * TT];

// ---------------------------------------------------------------------------
// Low-level helpers
// ---------------------------------------------------------------------------
__device__ __forceinline__ void cp_async16(uint32_t dst, const void* src, int bytes) {
    asm volatile("cp.async.ca.shared.global [%0], [%1], 16, %2;\n"
                 :: "r"(dst), "l"(src), "r"(bytes));
}
__device__ __forceinline__ void cp_commit() {
    asm volatile("cp.async.commit_group;\n" ::: "memory");
}
template <int N>
__device__ __forceinline__ void cp_wait() {
    asm volatile("cp.async.wait_group %0;\n" :: "n"(N) : "memory");
}

__device__ __forceinline__ void ldsm4(uint32_t (&r)[4], uint32_t addr) {
    asm volatile("ldmatrix.sync.aligned.m8n8.x4.shared.b16 {%0,%1,%2,%3}, [%4];"
                 : "=r"(r[0]), "=r"(r[1]), "=r"(r[2]), "=r"(r[3]) : "r"(addr));
}

__device__ __forceinline__ void mma_f16(float (&c)[4], const uint32_t (&a)[4],
                                        uint32_t b0, uint32_t b1) {
    asm volatile(
        "mma.sync.aligned.m16n8k16.row.col.f32.f16.f16.f32 "
        "{%0,%1,%2,%3}, {%4,%5,%6,%7}, {%8,%9}, {%0,%1,%2,%3};\n"
        : "+f"(c[0]), "+f"(c[1]), "+f"(c[2]), "+f"(c[3])
        : "r"(a[0]), "r"(a[1]), "r"(a[2]), "r"(a[3]), "r"(b0), "r"(b1));
}

__device__ __forceinline__ unsigned ld_acq(const unsigned* p) {
    unsigned v;
    asm volatile("ld.acquire.gpu.global.u32 %0, [%1];"
                 : "=r"(v) : "l"(p) : "memory");
    return v;
}

// 256-bit L2 policy-hinted loads (sm_100a requires v8.b32 for evict hints)
__device__ __forceinline__ void ldg_keep8(const uint32_t* p, uint32_t* v) {
    asm("ld.global.L2::evict_last.v8.b32 {%0,%1,%2,%3,%4,%5,%6,%7}, [%8];"
        : "=r"(v[0]), "=r"(v[1]), "=r"(v[2]), "=r"(v[3]),
          "=r"(v[4]), "=r"(v[5]), "=r"(v[6]), "=r"(v[7]) : "l"(p));
}
__device__ __forceinline__ void ldg_stream8(const uint32_t* p, uint32_t* v) {
    asm("ld.global.L2::evict_first.v8.b32 {%0,%1,%2,%3,%4,%5,%6,%7}, [%8];"
        : "=r"(v[0]), "=r"(v[1]), "=r"(v[2]), "=r"(v[3]),
          "=r"(v[4]), "=r"(v[5]), "=r"(v[6]), "=r"(v[7]) : "l"(p));
}

// f16x2 ops for the attention scores phase
__device__ __forceinline__ uint32_t hadd2_(uint32_t a, uint32_t b) {
    uint32_t d;
    asm("add.f16x2 %0, %1, %2;" : "=r"(d) : "r"(a), "r"(b));
    return d;
}
__device__ __forceinline__ uint32_t hfma2_(uint32_t a, uint32_t b, uint32_t c) {
    uint32_t d;
    asm("fma.rn.f16x2 %0, %1, %2, %3;" : "=r"(d) : "r"(a), "r"(b), "r"(c));
    return d;
}
__device__ __forceinline__ uint32_t tanh2_(uint32_t x) {
    uint32_t d;
    asm("tanh.approx.f16x2 %0, %1;" : "=r"(d) : "r"(x));
    return d;
}

__device__ __forceinline__ float sigmoid_fast(float x) {
    return __fdividef(1.0f, 1.0f + __expf(-x));
}
__device__ __forceinline__ float tanh_fast(float x) {
    x = fminf(15.0f, fmaxf(-15.0f, x));
    float e = __expf(2.0f * x);
    return 1.0f - __fdividef(2.0f, e + 1.0f);
}

__device__ __forceinline__ float warpMax(float v) {
    #pragma unroll
    for (int o = 16; o; o >>= 1) v = fmaxf(v, __shfl_xor_sync(0xffffffffu, v, o));
    return v;
}
__device__ __forceinline__ float warpSum(float v) {
    #pragma unroll
    for (int o = 16; o; o >>= 1) v += __shfl_xor_sync(0xffffffffu, v, o);
    return v;
}
__device__ __forceinline__ float blockMax(float v, float* red) {
    v = warpMax(v);
    int w = threadIdx.x >> 5, l = threadIdx.x & 31, nw = blockDim.x >> 5;
    if (l == 0) red[w] = v;
    __syncthreads();
    if (threadIdx.x < 32) {
        float x = (threadIdx.x < nw) ? red[threadIdx.x] : -INFINITY;
        x = warpMax(x);
        if (threadIdx.x == 0) red[0] = x;
    }
    __syncthreads();
    v = red[0];
    __syncthreads();
    return v;
}
__device__ __forceinline__ float blockSum(float v, float* red) {
    v = warpSum(v);
    int w = threadIdx.x >> 5, l = threadIdx.x & 31, nw = blockDim.x >> 5;
    if (l == 0) red[w] = v;
    __syncthreads();
    if (threadIdx.x < 32) {
        float x = (threadIdx.x < nw) ? red[threadIdx.x] : 0.0f;
        x = warpSum(x);
        if (threadIdx.x == 0) red[0] = x;
    }
    __syncthreads();
    v = red[0];
    __syncthreads();
    return v;
}

// ---------------------------------------------------------------------------
// cvt_all: every fp32->fp16 repack + s copy + zeroing, in ONE launch.
// ---------------------------------------------------------------------------
struct CvtArgs {
    const float* enc;
    const float* embed;
    const float* W_ih;
    const float* W_hh;
    const float* att_Ws;
    const float* att_Wh;
    const float* read_W;
    const float* read_Wo;
    const float* s_in;
};

__device__ __forceinline__ void cvt_job(
    const float* __restrict__ src, __half* __restrict__ dst,
    int rows, int sstr, int soff, int dstr, int clen)
{
    int total = rows * dstr;
    for (int i = blockIdx.x * blockDim.x + threadIdx.x; i < total;
         i += gridDim.x * blockDim.x) {
        int r = i / dstr, c = i - r * dstr;
        float v = (c < clen) ? src[(size_t)r * sstr + soff + c] : 0.0f;
        dst[i] = __float2half(v);
    }
}

__global__ __launch_bounds__(256) void cvt_all(CvtArgs a) {
    switch (blockIdx.y) {
    case 0:  cvt_job(a.enc,     g_enc_h,   BB * LL, 512, 0, 512, 512); break;
    case 1:  cvt_job(a.embed,   g_embed_h, VV, 300, 0, 304, 300); break;
    case 2:  cvt_job(a.W_ih,    g_Wih_e,   1536, 812, 0, 304, 300); break;
    case 3:  cvt_job(a.W_ih,    g_Wih_c,   1536, 812, 300, 512, 512); break;
    case 4:  cvt_job(a.W_hh,    g_Whh,     1536, 512, 0, 512, 512); break;
    case 5:  cvt_job(a.att_Ws,  g_Ws,      512, 512, 0, 512, 512); break;
    case 6:  cvt_job(a.att_Wh,  g_Wh,      512, 512, 0, 512, 512); break;
    case 7:  cvt_job(a.read_W,  g_Wr_e,    512, 1324, 0, 304, 300); break;
    case 8:  cvt_job(a.read_W,  g_Wr_c,    512, 1324, 300, 1024, 1024); break;
    case 9:  cvt_job(a.read_Wo, g_Wo,      VV, 256, 0, 256, 256); break;
    case 10: cvt_job(a.s_in,    g_shh,     BB, 512, 0, 512, 512); break;
    case 11: {
        for (int i = blockIdx.x * blockDim.x + threadIdx.x; i < BB * HD;
             i += gridDim.x * blockDim.x)
            g_sf[i] = a.s_in[i];
        break;
    }
    case 12: {
        for (int i = blockIdx.x * blockDim.x + threadIdx.x; i < BB * HE;
             i += gridDim.x * blockDim.x)
            g_chh[i] = __float2half(0.0f);
        break;
    }
    default: {
        for (int i = blockIdx.x * blockDim.x + threadIdx.x; i < 3 * TT;
             i += gridDim.x * blockDim.x)
            g_cnt[i] = 0u;
        break;
    }
    }
}

// ---------------------------------------------------------------------------
// 64x64-tile fp16 GEMM (128 threads), explicit tile coords
// ---------------------------------------------------------------------------
struct GH {
    const __half* A; int lda;
    const __half* W; int ldw;
    float* C; int ldc;
    int N;
    int kbeg, kend;
    const __half* embed;
    const int*    tgt;
    const __half* ctx;
    const __half* s;
};

#define MODE_PLAIN 0
#define MODE_EMB   1
#define MODE_CS    2

template <int MODE, bool OUTH>
__device__ __forceinline__ void grun(const GH& g, int mt0, int nt0) {
    extern __shared__ __half smh[];
    __half* As = smh;
    __half* Ws = smh + STAGES * 64 * SK;

    const int tid = threadIdx.x, lane = tid & 31, warp = tid >> 5;
    const int wm = warp >> 1, wn = warp & 1;

    const int r0 = tid >> 2, kc = (tid & 3) * 8;
    const int r1 = r0 + 32;
    const int gm0 = mt0 + r0, gm1 = mt0 + r1;
    const int gn0 = nt0 + r0, gn1 = nt0 + r1;

    const __half *a0 = nullptr, *a1 = nullptr;
    const __half *c0p = nullptr, *c1p = nullptr, *s0p = nullptr, *s1p = nullptr;
    if (MODE == MODE_PLAIN) {
        a0 = g.A + (size_t)gm0 * g.lda;
        a1 = g.A + (size_t)gm1 * g.lda;
    } else if (MODE == MODE_EMB) {
        int t0 = gm0 >> 7, b0 = gm0 & 127;
        int w0 = (t0 == 0) ? SOS_ID : g.tgt[b0 * TT + t0 - 1];
        if (w0 >= VV) w0 = UNK_ID;
        int t1 = gm1 >> 7, b1 = gm1 & 127;
        int w1 = (t1 == 0) ? SOS_ID : g.tgt[b1 * TT + t1 - 1];
        if (w1 >= VV) w1 = UNK_ID;
        a0 = g.embed + (size_t)w0 * 304;
        a1 = g.embed + (size_t)w1 * 304;
    } else {
        c0p = g.ctx + (size_t)gm0 * 512; c1p = g.ctx + (size_t)gm1 * 512;
        s0p = g.s   + (size_t)gm0 * 512; s1p = g.s   + (size_t)gm1 * 512;
    }
    const bool n0ok = (gn0 < g.N), n1ok = (gn1 < g.N);
    const __half* w0p = g.W + (size_t)(n0ok ? gn0 : 0) * g.ldw;
    const __half* w1p = g.W + (size_t)(n1ok ? gn1 : 0) * g.ldw;

    const uint32_t asB = (uint32_t)__cvta_generic_to_shared(As);
    const uint32_t wsB = (uint32_t)__cvta_generic_to_shared(Ws);
    const int STB = 64 * SK * 2;
    const uint32_t aD0 = asB + (r0 * SK + kc) * 2;
    const uint32_t aD1 = asB + (r1 * SK + kc) * 2;
    const uint32_t wD0 = wsB + (r0 * SK + kc) * 2;
    const uint32_t wD1 = wsB + (r1 * SK + kc) * 2;

    const int nk = (g.kend - g.kbeg + 31) >> 5;

    auto pf = [&](int i) {
        int kg = g.kbeg + i * 32 + kc;
        int buf = (i & 3) * STB;
        bool v = kg < g.kend;
        const __half *sa0, *sa1;
        if (MODE == MODE_CS) {
            sa0 = (kg < 512) ? c0p + kg : s0p + (kg - 512);
            sa1 = (kg < 512) ? c1p + kg : s1p + (kg - 512);
        } else {
            sa0 = a0 + kg; sa1 = a1 + kg;
        }
        if (!v) { sa0 = g.W; sa1 = g.W; }
        cp_async16(aD0 + buf, sa0, v ? 16 : 0);
        cp_async16(aD1 + buf, sa1, v ? 16 : 0);
        bool v0 = v && n0ok, v1 = v && n1ok;
        cp_async16(wD0 + buf, v0 ? (w0p + kg) : g.W, v0 ? 16 : 0);
        cp_async16(wD1 + buf, v1 ? (w1p + kg) : g.W, v1 ? 16 : 0);
    };

    #pragma unroll
    for (int p = 0; p < 3; p++) {
        if (p < nk) pf(p);
        cp_commit();
    }

    float c[2][4][4] = {};
    const int lr = lane & 15, lk = (lane >> 4) * 8;

    for (int i = 0; i < nk; i++) {
        if (i + 3 < nk) pf(i + 3);
        cp_commit();
        cp_wait<3>();
        __syncthreads();

        const uint32_t ab = asB + (i & 3) * STB;
        const uint32_t wb = wsB + (i & 3) * STB;

        #pragma unroll
        for (int kk = 0; kk < 32; kk += 16) {
            uint32_t a[2][4], bb[2][4];
            #pragma unroll
            for (int mt = 0; mt < 2; mt++)
                ldsm4(a[mt], ab + ((wm * 32 + mt * 16 + lr) * SK + kk + lk) * 2);
            #pragma unroll
            for (int n2 = 0; n2 < 2; n2++)
                ldsm4(bb[n2], wb + ((wn * 32 + n2 * 16 + lr) * SK + kk + lk) * 2);
            #pragma unroll
            for (int mt = 0; mt < 2; mt++)
                #pragma unroll
                for (int ns = 0; ns < 4; ns++) {
                    int n2 = ns >> 1, sel = ns & 1;
                    mma_f16(c[mt][ns], a[mt], bb[n2][sel], bb[n2][sel + 2]);
                }
        }
        __syncthreads();
    }

    const int gr = lane >> 2, gc = (lane & 3) * 2;
    #pragma unroll
    for (int mt = 0; mt < 2; mt++)
        #pragma unroll
        for (int ns = 0; ns < 4; ns++) {
            int row = mt0 + wm * 32 + mt * 16 + gr;
            int col = nt0 + wn * 32 + ns * 8 + gc;
            if (col < g.N) {
                if (OUTH) {
                    __half* Ch = (__half*)g.C;
                    Ch[(size_t)row * g.ldc + col]           = __float2half(c[mt][ns][0]);
                    Ch[(size_t)row * g.ldc + col + 1]       = __float2half(c[mt][ns][1]);
                    Ch[(size_t)(row + 8) * g.ldc + col]     = __float2half(c[mt][ns][2]);
                    Ch[(size_t)(row + 8) * g.ldc + col + 1] = __float2half(c[mt][ns][3]);
                } else {
                    g.C[(size_t)row * g.ldc + col]           = c[mt][ns][0];
                    g.C[(size_t)row * g.ldc + col + 1]       = c[mt][ns][1];
                    g.C[(size_t)(row + 8) * g.ldc + col]     = c[mt][ns][2];
                    g.C[(size_t)(row + 8) * g.ldc + col + 1] = c[mt][ns][3];
                }
            }
        }
}

__global__ __launch_bounds__(128) void k_g_plain(GH g) {
    grun<MODE_PLAIN, false>(g, blockIdx.y * 64, blockIdx.x * 64);
}
__global__ __launch_bounds__(128) void k_g_cs(GH g) {
    grun<MODE_CS, false>(g, blockIdx.y * 64, blockIdx.x * 64);
}

// All three precompute GEMMs in ONE launch (flattened grid)
__global__ __launch_bounds__(128) void k_uber(GH gp, GH ge, GH gr) {
    int bid = blockIdx.x;
    if (bid < 6400) {           // proj: 8 x 800 tiles
        grun<MODE_PLAIN, true>(gp, (bid / 8) * 64, (bid % 8) * 64);
    } else if (bid < 7840) {    // giemb: 24 x 60 tiles
        int j = bid - 6400;
        grun<MODE_EMB, false>(ge, (j / 24) * 64, (j % 24) * 64);
    } else {                    // rvemb: 8 x 60 tiles
        int j = bid - 7840;
        grun<MODE_EMB, false>(gr, (j / 8) * 64, (j % 8) * 64);
    }
}

// ---------------------------------------------------------------------------
// 128x128-tile fp16 GEMM (512 threads, 2-stage) — used inside step_kernel.
// ---------------------------------------------------------------------------
__device__ __forceinline__ void grun512(
    const __half* __restrict__ A, int lda,
    const __half* __restrict__ W, int ldw,
    float* __restrict__ C, int ldc, int N,
    int kbeg, int kend, int nt0)
{
    extern __shared__ __half smh[];
    __half* As = smh;
    __half* Ws = smh + 2 * 128 * SK;

    const int tid = threadIdx.x, lane = tid & 31, warp = tid >> 5;
    const int wm = warp >> 2, wn = warp & 3;

    const int r = tid >> 2, kc = (tid & 3) * 8;
    const __half* aRow = A + (size_t)r * lda;
    const int gn = nt0 + r;
    const bool nok = (gn < N);
    const __half* wRow = W + (size_t)(nok ? gn : 0) * ldw;

    const uint32_t asB = (uint32_t)__cvta_generic_to_shared(As);
    const uint32_t wsB = (uint32_t)__cvta_generic_to_shared(Ws);
    const int STB = 128 * SK * 2;
    const uint32_t aD = asB + (r * SK + kc) * 2;
    const uint32_t wD = wsB + (r * SK + kc) * 2;

    const int nk = (kend - kbeg + 31) >> 5;

    auto pf = [&](int i) {
        int kg = kbeg + i * 32 + kc;
        int buf = (i & 1) * STB;
        bool v = kg < kend;
        cp_async16(aD + buf, v ? (const void*)(aRow + kg) : (const void*)W,
                   v ? 16 : 0);
        bool vw = v && nok;
        cp_async16(wD + buf, vw ? (const void*)(wRow + kg) : (const void*)W,
                   vw ? 16 : 0);
    };

    pf(0);
    cp_commit();

    float c[2][4][4] = {};
    const int lr = lane & 15, lk = (lane >> 4) * 8;

    for (int i = 0; i < nk; i++) {
        if (i + 1 < nk) pf(i + 1);
        cp_commit();
        cp_wait<1>();
        __syncthreads();

        const uint32_t ab = asB + (i & 1) * STB;
        const uint32_t wb = wsB + (i & 1) * STB;

        #pragma unroll
        for (int kk = 0; kk < 32; kk += 16) {
            uint32_t a[2][4], bb[2][4];
            #pragma unroll
            for (int mt = 0; mt < 2; mt++)
                ldsm4(a[mt], ab + ((wm * 32 + mt * 16 + lr) * SK + kk + lk) * 2);
            #pragma unroll
            for (int n2 = 0; n2 < 2; n2++)
                ldsm4(bb[n2], wb + ((wn * 32 + n2 * 16 + lr) * SK + kk + lk) * 2);
            #pragma unroll
            for (int mt = 0; mt < 2; mt++)
                #pragma unroll
                for (int ns = 0; ns < 4; ns++) {
                    int n2 = ns >> 1, sel = ns & 1;
                    mma_f16(c[mt][ns], a[mt], bb[n2][sel], bb[n2][sel + 2]);
                }
        }
        __syncthreads();
    }

    const int gr = lane >> 2, gc = (lane & 3) * 2;
    #pragma unroll
    for (int mt = 0; mt < 2; mt++)
        #pragma unroll
        for (int ns = 0; ns < 4; ns++) {
            int row = wm * 32 + mt * 16 + gr;
            int col = nt0 + wn * 32 + ns * 8 + gc;
            if (col < N) {
                C[(size_t)row * ldc + col]           = c[mt][ns][0];
                C[(size_t)row * ldc + col + 1]       = c[mt][ns][1];
                C[(size_t)(row + 8) * ldc + col]     = c[mt][ns][2];
                C[(size_t)(row + 8) * ldc + col + 1] = c[mt][ns][3];
            }
        }
}

// ---------------------------------------------------------------------------
// step_kernel: all 4 phases of one decoder step in one launch.
// bid 0..95 gates | 96..127 gru | 128..143 q | 144..271 attention
// ---------------------------------------------------------------------------
__global__ __launch_bounds__(512) void step_kernel(
    int t,
    const float* __restrict__ b_ih, const float* __restrict__ b_hh,
    const float* __restrict__ att_b, const float* __restrict__ vvec,
    const int*   __restrict__ src,
    const float* __restrict__ copy_W, const float* __restrict__ copy_b)
{
    __shared__ __align__(16) float es[LL];
    __shared__ float red[32];

    const int bid = blockIdx.x, tid = threadIdx.x;
    const __half* shC = g_shh + (size_t)t * BB * HD;
    __half*       shN = g_shh + (size_t)(t + 1) * BB * HD;
    const __half* chC = g_chh + (size_t)t * BB * HE;
    __half*       chN = g_chh + (size_t)(t + 1) * BB * HE;
    const float*  sCur = g_sf + (size_t)t * BB * HD;
    float*        sNxt = g_sf + (size_t)(t + 1) * BB * HD;

    if (bid < 96) {
        // ---- Phase A: gates GEMMs ----
        int half = bid / 48, j = bid % 48;
        int sp = j / 12, nt = j % 12;
        const __half* A = half ? shC : chC;
        const __half* W = half ? g_Whh : g_Wih_c;
        float* C = (half ? g_gh_p : g_gi_p) + (size_t)sp * BB * 1536;
        grun512(A, 512, W, 512, C, 1536, 1536, sp * 128, sp * 128 + 128,
                nt * 128);
        __threadfence();
        __syncthreads();
        if (tid == 0) atomicAdd(&g_cnt[t], 1u);
    } else if (bid < 128) {
        // ---- Phase B: GRU ----
        if (tid == 0) {
            while (ld_acq(&g_cnt[t]) < 96u) __nanosleep(64);
        }
        __syncthreads();
        for (int i = (bid - 96) * 512 + tid; i < BB * HD; i += 32 * 512) {
            int b = i >> 9, h = i & 511;
            size_t ob = (size_t)b * 1536;
            size_t oe = ((size_t)t * BB + b) * 1536;
            float ir = g_giemb[oe + h]        + b_ih[h];
            float iz = g_giemb[oe + 512 + h]  + b_ih[512 + h];
            float in = g_giemb[oe + 1024 + h] + b_ih[1024 + h];
            float hr = b_hh[h], hz = b_hh[512 + h], hn = b_hh[1024 + h];
            #pragma unroll
            for (int z = 0; z < 4; z++) {
                size_t o = (size_t)z * BB * 1536 + ob;
                ir += g_gi_p[o + h];        iz += g_gi_p[o + 512 + h];
                in += g_gi_p[o + 1024 + h];
                hr += g_gh_p[o + h];        hz += g_gh_p[o + 512 + h];
                hn += g_gh_p[o + 1024 + h];
            }
            float r = sigmoid_fast(ir + hr);
            float z = sigmoid_fast(iz + hz);
            float n = tanh_fast(in + r * hn);
            float sn = (1.0f - z) * n + z * sCur[i];
            sNxt[i] = sn;
            shN[i] = __float2half(sn);
        }
        __threadfence();
        __syncthreads();
        if (tid == 0) atomicAdd(&g_cnt[TT + t], 1u);
    } else if (bid < 144) {
        // ---- Phase C: q split-K4 GEMM ----
        if (tid == 0) {
            while (ld_acq(&g_cnt[TT + t]) < 32u) __nanosleep(64);
        }
        __syncthreads();
        int j = bid - 128, sp = j >> 2, nt = j & 3;
        grun512(shN, 512, g_Ws, 512, g_qp + (size_t)sp * BB * 512, 512, 512,
                sp * 128, sp * 128 + 128, nt * 128);
        __threadfence();
        __syncthreads();
        if (tid == 0) atomicAdd(&g_cnt[2 * TT + t], 1u);
    } else {
        // ---- Phase D: attention (L2-resident proj + streaming enc) ----
        extern __shared__ __half smh[];
        float* part = (float*)smh;              // [16][512] fp32 = 32 KB
        int b = bid - 144;
        if (tid == 0) {
            while (ld_acq(&g_cnt[2 * TT + t]) < 16u) __nanosleep(64);
        }
        __syncthreads();

        int warp = tid >> 5, lane = tid & 31;
        float* atT = g_attnb + (size_t)t * BB * LL;
        float* pcT = g_pcb + (size_t)t * BB;

        // q (bias + 4 partials) and v as half2 registers, lane owns 16 halves
        uint32_t qh[8], vh[8];
        {
            int base = lane * 16;
            float qf[16];
            #pragma unroll
            for (int p = 0; p < 16; p++) qf[p] = att_b[base + p];
            #pragma unroll
            for (int z = 0; z < 4; z++) {
                const float* qz = g_qp + ((size_t)z * BB + b) * 512 + base;
                #pragma unroll
                for (int q4 = 0; q4 < 4; q4++) {
                    float4 qv = *(const float4*)(qz + q4 * 4);
                    qf[q4 * 4]     += qv.x;
                    qf[q4 * 4 + 1] += qv.y;
                    qf[q4 * 4 + 2] += qv.z;
                    qf[q4 * 4 + 3] += qv.w;
                }
            }
            #pragma unroll
            for (int p = 0; p < 8; p++) {
                __half2 h = __floats2half2_rn(qf[2 * p], qf[2 * p + 1]);
                qh[p] = *(uint32_t*)&h;
                __half2 vv2 = __floats2half2_rn(vvec[base + 2 * p],
                                                vvec[base + 2 * p + 1]);
                vh[p] = *(uint32_t*)&vv2;
            }
        }

        // scores: warp owns rows [warp*25, warp*25+25); one 32B keep-load/row
        auto scoreRow = [&](const uint32_t* ha) -> float {
            uint32_t acc0 = 0u, acc1 = 0u;
            #pragma unroll
            for (int p = 0; p < 4; p++)
                acc0 = hfma2_(tanh2_(hadd2_(ha[p], qh[p])), vh[p], acc0);
            #pragma unroll
            for (int p = 4; p < 8; p++)
                acc1 = hfma2_(tanh2_(hadd2_(ha[p], qh[p])), vh[p], acc1);
            float2 f0 = __half22float2(*(__half2*)&acc0);
            float2 f1 = __half22float2(*(__half2*)&acc1);
            return (f0.x + f0.y) + (f1.x + f1.y);
        };

        const uint32_t* pb = (const uint32_t*)(g_proj_h + (size_t)b * LL * AA);
        const int r0w = warp * 25;
        #pragma unroll 1
        for (int c = 0; c < 6; c++) {
            int l = r0w + c * 4;
            uint32_t a0[8], a1[8], a2[8], a3[8];
            ldg_keep8(pb + (size_t)(l + 0) * 256 + lane * 8, a0);
            ldg_keep8(pb + (size_t)(l + 1) * 256 + lane * 8, a1);
            ldg_keep8(pb + (size_t)(l + 2) * 256 + lane * 8, a2);
            ldg_keep8(pb + (size_t)(l + 3) * 256 + lane * 8, a3);
            float s0 = scoreRow(a0);
            float s1 = scoreRow(a1);
            float s2 = scoreRow(a2);
            float s3 = scoreRow(a3);
            s0 = warpSum(s0); s1 = warpSum(s1);
            s2 = warpSum(s2); s3 = warpSum(s3);
            if (lane == 0) {
                es[l]     = s0;
                es[l + 1] = s1;
                es[l + 2] = s2;
                es[l + 3] = s3;
            }
        }
        {   // final row (r0w + 24)
            int l = r0w + 24;
            uint32_t a0[8];
            ldg_keep8(pb + (size_t)l * 256 + lane * 8, a0);
            float s0 = warpSum(scoreRow(a0));
            if (lane == 0) es[l] = s0;
        }
        __syncthreads();

        // softmax over L (pad mask applied here)
        float ev = -INFINITY;
        if (tid < LL)
            ev = (src[b * LL + tid] == PAD_ID) ? -1e30f : es[tid];
        float m  = blockMax(ev, red);
        float p  = (tid < LL) ? __expf(ev - m) : 0.0f;
        float Z  = blockSum(p, red);
        float a  = p / Z;
        if (tid < LL) { es[tid] = a; atT[b * LL + tid] = a; }
        __syncthreads();

        // ctx: 16 groups x 32 threads; thread owns 16 columns; 32B stream-loads
        int gg = tid >> 5, cc = tid & 31;
        const uint32_t* eb = (const uint32_t*)(g_enc_h + (size_t)b * LL * HE)
                           + cc * 8;
        float acc[16] = {};
        int l0 = gg * 25;
        auto accRow = [&](const uint32_t* v, float w) {
            #pragma unroll
            for (int p = 0; p < 8; p++) {
                float2 f = __half22float2(*(const __half2*)&v[p]);
                acc[2 * p]     += w * f.x;
                acc[2 * p + 1] += w * f.y;
            }
        };
        #pragma unroll 1
        for (int c = 0; c < 12; c++) {
            int l = l0 + c * 2;
            uint32_t v0[8], v1[8];
            ldg_stream8(eb + (size_t)(l + 0) * 256, v0);
            ldg_stream8(eb + (size_t)(l + 1) * 256, v1);
            accRow(v0, es[l]);
            accRow(v1, es[l + 1]);
        }
        {   // remainder row l0+24
            uint32_t v0[8];
            ldg_stream8(eb + (size_t)(l0 + 24) * 256, v0);
            accRow(v0, es[l0 + 24]);
        }
        #pragma unroll
        for (int p = 0; p < 16; p++)
            part[gg * 512 + cc * 16 + p] = acc[p];
        __syncthreads();

        float ctxv = 0.0f;
        #pragma unroll
        for (int g2 = 0; g2 < 16; g2++)
            ctxv += part[g2 * 512 + tid];
        chN[b * HE + tid] = __float2half(ctxv);

        // p_copy
        float pp_ = sNxt[b * HD + tid] * copy_W[tid] + ctxv * copy_W[HD + tid];
        float tot = blockSum(pp_, red);
        if (tid == 0) pcT[b] = sigmoid_fast(tot + copy_b[0]);
    }
}

// ---------------------------------------------------------------------------
// Batched tail (per chunk of steps)
// ---------------------------------------------------------------------------
__global__ __launch_bounds__(256) void mred_all(
    const float* __restrict__ rv, const float* __restrict__ rvemb,
    const float* __restrict__ read_b, __half* __restrict__ mh)
{
    int idx = blockIdx.x * 256 + threadIdx.x;
    int row = idx >> 8, c = idx & 255;
    size_t o = (size_t)row * 512;
    float r0 = rv[o + 2 * c]     + rvemb[o + 2 * c]     + read_b[2 * c];
    float r1 = rv[o + 2 * c + 1] + rvemb[o + 2 * c + 1] + read_b[2 * c + 1];
    mh[idx] = __float2half(fmaxf(r0, r1));
}

__global__ __launch_bounds__(1024) void output_all(
    const float* __restrict__ energy,
    const float* __restrict__ attnb,
    const float* __restrict__ pcb,
    float* __restrict__ out, int row0)
{
    __shared__ float red[32];
    int row = row0 + blockIdx.x;          // t*128 + b
    int t = row >> 7, b = row & 127;
    int tid = threadIdx.x;
    const float4* eb4 = (const float4*)(energy + (size_t)row * VV);

    float mx = -INFINITY;
    for (int j = tid; j < VV / 4; j += 1024) {
        float4 v = eb4[j];
        mx = fmaxf(mx, fmaxf(fmaxf(v.x, v.y), fmaxf(v.z, v.w)));
    }
    mx = blockMax(mx, red);

    float sm = 0.0f;
    for (int j = tid; j < VV / 4; j += 1024) {
        float4 v = eb4[j];
        sm += __expf(v.x - mx) + __expf(v.y - mx) + __expf(v.z - mx) + __expf(v.w - mx);
    }
    sm = blockSum(sm, red);

    float pc = pcb[row];
    float scale = (1.0f - pc) / sm;
    float* ob = out + ((size_t)b * TT + t) * (VV + LL);
    float4* ob4 = (float4*)ob;
    for (int j = tid; j < VV / 4; j += 1024) {
        float4 v = eb4[j], o;
        o.x = __logf(__expf(v.x - mx) * scale + 1e-12f);
        o.y = __logf(__expf(v.y - mx) * scale + 1e-12f);
        o.z = __logf(__expf(v.z - mx) * scale + 1e-12f);
        o.w = __logf(__expf(v.w - mx) * scale + 1e-12f);
        ob4[j] = o;
    }
    const float4* at4 = (const float4*)(attnb + (size_t)row * LL);
    float4* oc4 = (float4*)(ob + VV);
    for (int j = tid; j < LL / 4; j += 1024) {
        float4 a = at4[j], o;
        o.x = __logf(fmaf(pc, a.x, 1e-12f));
        o.y = __logf(fmaf(pc, a.y, 1e-12f));
        o.z = __logf(fmaf(pc, a.z, 1e-12f));
        o.w = __logf(fmaf(pc, a.w, 1e-12f));
        oc4[j] = o;
    }
}

// ---------------------------------------------------------------------------
// Host orchestration
// ---------------------------------------------------------------------------
extern "C" void kernel_launch(void* const* d_in, const int* in_sizes, int n_in,
                              void* d_out, int out_size)
{
    const float* enc     = (const float*)d_in[0];
    const float* s_in    = (const float*)d_in[1];
    const int*   src     = (const int*)  d_in[2];
    const int*   tgt     = (const int*)  d_in[3];
    const float* embed   = (const float*)d_in[4];
    const float* W_ih    = (const float*)d_in[5];
    const float* b_ih    = (const float*)d_in[6];
    const float* W_hh    = (const float*)d_in[7];
    const float* b_hh    = (const float*)d_in[8];
    const float* att_Wh  = (const float*)d_in[9];
    const float* att_Ws  = (const float*)d_in[10];
    const float* att_b   = (const float*)d_in[11];
    const float* att_v   = (const float*)d_in[12];
    const float* copy_W  = (const float*)d_in[13];
    const float* copy_b  = (const float*)d_in[14];
    const float* read_W  = (const float*)d_in[15];
    const float* read_b  = (const float*)d_in[16];
    const float* read_Wo = (const float*)d_in[17];
    float* out = (float*)d_out;

    __half *p_ench, *p_projh, *p_embh, *p_Wihe, *p_Wre, *p_Wrc, *p_Wo;
    __half *p_Wh, *p_shh, *p_chh, *p_mh;
    float *p_giemb, *p_rvemb, *p_rv, *p_attn, *p_pc, *p_energy;

    cudaGetSymbolAddress((void**)&p_ench,  g_enc_h);
    cudaGetSymbolAddress((void**)&p_projh, g_proj_h);
    cudaGetSymbolAddress((void**)&p_embh,  g_embed_h);
    cudaGetSymbolAddress((void**)&p_Wihe,  g_Wih_e);
    cudaGetSymbolAddress((void**)&p_Wh,    g_Wh);
    cudaGetSymbolAddress((void**)&p_Wre,   g_Wr_e);
    cudaGetSymbolAddress((void**)&p_Wrc,   g_Wr_c);
    cudaGetSymbolAddress((void**)&p_Wo,    g_Wo);
    cudaGetSymbolAddress((void**)&p_giemb, g_giemb);
    cudaGetSymbolAddress((void**)&p_rvemb, g_rvemb);
    cudaGetSymbolAddress((void**)&p_shh,   g_shh);
    cudaGetSymbolAddress((void**)&p_chh,   g_chh);
    cudaGetSymbolAddress((void**)&p_attn,  g_attnb);
    cudaGetSymbolAddress((void**)&p_pc,    g_pcb);
    cudaGetSymbolAddress((void**)&p_rv,    g_rv_all);
    cudaGetSymbolAddress((void**)&p_mh,    g_mh_all);
    cudaGetSymbolAddress((void**)&p_energy,g_energy_all);

    cudaStream_t side;
    cudaStreamCreateWithFlags(&side, cudaStreamNonBlocking);
    cudaEvent_t evF, evJ;
    cudaEventCreateWithFlags(&evF, cudaEventDisableTiming);
    cudaEventCreateWithFlags(&evJ, cudaEventDisableTiming);

    // ---- Launch 0: ALL conversions + init ----
    {
        CvtArgs a{enc, embed, W_ih, W_hh, att_Ws, att_Wh, read_W, read_Wo, s_in};
        cvt_all<<<dim3(1024, 14), 256>>>(a);
    }

    // ---- Launch 1: ALL precompute GEMMs in one kernel ----
    {
        GH gp{}; gp.A = p_ench; gp.lda = HE; gp.W = p_Wh; gp.ldw = 512;
        gp.C = (float*)p_projh; gp.ldc = AA; gp.N = AA;
        gp.kbeg = 0; gp.kend = 512;
        GH ge{}; ge.embed = p_embh; ge.tgt = tgt; ge.W = p_Wihe; ge.ldw = 304;
        ge.C = p_giemb; ge.ldc = 1536; ge.N = 1536;
        ge.kbeg = 0; ge.kend = 304;
        GH gr{}; gr.embed = p_embh; gr.tgt = tgt; gr.W = p_Wre; gr.ldw = 304;
        gr.C = p_rvemb; gr.ldc = 512; gr.N = 512;
        gr.kbeg = 0; gr.kend = 304;
        k_uber<<<8320, 128, SMEM_GEMM>>>(gp, ge, gr);
    }

    // Tail-chunk launcher (stream st, steps [t0, t0+ns))
    auto tail_chunk = [&](cudaStream_t st, int t0, int ns) {
        int rows = ns * BB;
        {   // rv = [ctx, s] @ Wr_c^T
            GH g{}; g.ctx = p_chh + (size_t)(t0 + 1) * BB * HE;
            g.s = p_shh + (size_t)(t0 + 1) * BB * HD;
            g.W = p_Wrc; g.ldw = 1024;
            g.C = p_rv + (size_t)t0 * BB * 512; g.ldc = 512; g.N = 512;
            g.kbeg = 0; g.kend = 1024;
            k_g_cs<<<dim3(8, rows / 64), 128, SMEM_GEMM, st>>>(g);
        }
        mred_all<<<rows, 256, 0, st>>>(
            p_rv + (size_t)t0 * BB * 512,
            p_rvemb + (size_t)t0 * BB * 512,
            read_b, p_mh + (size_t)t0 * BB * 256);
        {   // energy = m @ read_Wo^T
            GH g{}; g.A = p_mh + (size_t)t0 * BB * 256; g.lda = 256;
            g.W = p_Wo; g.ldw = 256;
            g.C = p_energy + (size_t)t0 * BB * VV; g.ldc = VV; g.N = VV;
            g.kbeg = 0; g.kend = 256;
            k_g_plain<<<dim3(313, rows / 64), 128, SMEM_GEMM, st>>>(g);
        }
        output_all<<<rows, 1024, 0, st>>>(p_energy, p_attn, p_pc, out, t0 * BB);
    };

    // ---- Launches 2..31: the recurrence ----
    for (int t = 0; t < TT; t++) {
        step_kernel<<<272, 512, SMEM_STEP>>>(t, b_ih, b_hh, att_b, att_v,
                                             src, copy_W, copy_b);
        if (t == CH1 - 1) {
            cudaEventRecord(evF, 0);
            cudaStreamWaitEvent(side, evF, 0);
            tail_chunk(side, 0, CH1);
        }
    }

    // ---- Tail chunk 2 (steps CH1..TT-1) on stream 0 ----
    tail_chunk(0, CH1, TT - CH1);

    // ---- Join side stream ----
    cudaEventRecord(evJ, side);
    cudaStreamWaitEvent(0, evJ, 0);
}